// round 6
// baseline (speedup 1.0000x reference)
#include <cuda_runtime.h>
#include <cuda_bf16.h>
#include <math.h>
#include <stdint.h>

#define T_  1024
#define B_  128
#define D_  512
#define H_  256
#define TB_ (T_ * B_)      // 131072
#define G4_ (4 * H_)       // 1024

// ---------------- scratch (device globals; no cudaMalloc allowed) ----------
__device__ __nv_bfloat16 g_xh [(size_t)TB_ * D_];   // x hi plane
__device__ __nv_bfloat16 g_xl [(size_t)TB_ * D_];   // x lo plane
__device__ __nv_bfloat16 g_hh [(size_t)TB_ * H_];   // tanh(fc) hi
__device__ __nv_bfloat16 g_hl [(size_t)TB_ * H_];   // tanh(fc) lo
__device__ float         g_gx [(size_t)TB_ * G4_];  // gate inputs f32
__device__ __nv_bfloat16 g_hsh[(size_t)TB_ * H_];   // recurrence out hi
__device__ __nv_bfloat16 g_hsl[(size_t)TB_ * H_];   // recurrence out lo
__device__ __nv_bfloat16 g_z0h[(size_t)TB_ * H_];
__device__ __nv_bfloat16 g_z0l[(size_t)TB_ * H_];
__device__ float         g_z1 [(size_t)TB_ * H_];
__device__ __nv_bfloat16 g_fwh[H_ * D_];            // fc_w hi/lo
__device__ __nv_bfloat16 g_fwl[H_ * D_];
__device__ __nv_bfloat16 g_Wxh[G4_ * H_];           // input gate weights hi/lo
__device__ __nv_bfloat16 g_Wxl[G4_ * H_];
__device__ float         g_Wh [G4_ * H_];           // recurrent weights f32
__device__ float         g_bias[G4_];
__device__ __nv_bfloat16 g_w0h[H_ * H_];
__device__ __nv_bfloat16 g_w0l[H_ * H_];
__device__ __nv_bfloat16 g_w1h[H_ * H_];
__device__ __nv_bfloat16 g_w1l[H_ * H_];

// ================= helpers ==================================================
__device__ __forceinline__ uint32_t smem_u32(const void* p) {
    uint32_t a;
    asm("{ .reg .u64 t; cvta.to.shared.u64 t, %1; cvt.u32.u64 %0, t; }"
        : "=r"(a) : "l"(p));
    return a;
}

__device__ __forceinline__ void mma_bf16(float* c, const uint32_t* a,
                                         const uint32_t* b) {
    asm volatile(
        "mma.sync.aligned.m16n8k16.row.col.f32.bf16.bf16.f32 "
        "{%0,%1,%2,%3}, {%4,%5,%6,%7}, {%8,%9}, {%0,%1,%2,%3};"
        : "+f"(c[0]), "+f"(c[1]), "+f"(c[2]), "+f"(c[3])
        : "r"(a[0]), "r"(a[1]), "r"(a[2]), "r"(a[3]), "r"(b[0]), "r"(b[1]));
}

__device__ __forceinline__ void ldsm4(uint32_t* d, uint32_t addr) {
    asm volatile("ldmatrix.sync.aligned.m8n8.x4.shared.b16 {%0,%1,%2,%3}, [%4];"
        : "=r"(d[0]), "=r"(d[1]), "=r"(d[2]), "=r"(d[3]) : "r"(addr));
}

__device__ __forceinline__ void cpa16(uint32_t d, const void* s) {
    asm volatile("cp.async.cg.shared.global [%0], [%1], 16;" :: "r"(d), "l"(s));
}
#define CP_COMMIT() asm volatile("cp.async.commit_group;" ::: "memory")
#define CP_WAIT1()  asm volatile("cp.async.wait_group 1;" ::: "memory")
#define CP_WAIT0()  asm volatile("cp.async.wait_group 0;" ::: "memory")

// packed dual fp32 FMA (SASS FFMA2)
__device__ __forceinline__ void fma2(unsigned long long& d,
                                     unsigned long long a,
                                     unsigned long long b) {
    asm("fma.rn.f32x2 %0, %1, %2, %0;" : "+l"(d) : "l"(a), "l"(b));
}

__device__ __forceinline__ void st_cluster_f32(uint32_t addr, uint32_t rank,
                                               float v) {
    uint32_t ra;
    asm volatile("mapa.shared::cluster.u32 %0, %1, %2;"
                 : "=r"(ra) : "r"(addr), "r"(rank));
    asm volatile("st.shared::cluster.f32 [%0], %1;" :: "r"(ra), "f"(v)
                 : "memory");
}
#define CLUSTER_SYNC() do { \
    asm volatile("barrier.cluster.arrive.aligned;" ::: "memory"); \
    asm volatile("barrier.cluster.wait.aligned;" ::: "memory"); } while (0)

// ---------------- split helpers --------------------------------------------
__device__ __forceinline__ void split1(float v, __nv_bfloat16& h,
                                       __nv_bfloat16& l) {
    h = __float2bfloat16_rn(v);
    l = __float2bfloat16_rn(v - __bfloat162float(h));
}

__global__ void splitpack_kernel(const float* __restrict__ s,
                                 __nv_bfloat16* __restrict__ hp,
                                 __nv_bfloat16* __restrict__ lp, int n4) {
    int i = blockIdx.x * 256 + threadIdx.x;
    if (i < n4) {
        float4 v = ((const float4*)s)[i];
        __nv_bfloat16 h0, h1, h2, h3, l0, l1, l2, l3;
        split1(v.x, h0, l0); split1(v.y, h1, l1);
        split1(v.z, h2, l2); split1(v.w, h3, l3);
        __nv_bfloat162* hp2 = (__nv_bfloat162*)&hp[i * 4];
        __nv_bfloat162* lp2 = (__nv_bfloat162*)&lp[i * 4];
        hp2[0] = __halves2bfloat162(h0, h1);
        hp2[1] = __halves2bfloat162(h2, h3);
        lp2[0] = __halves2bfloat162(l0, l1);
        lp2[1] = __halves2bfloat162(l2, l3);
    }
}

// ---------------- pack gate weights: rows [f|i|u|o], split x/h halves ------
__global__ void pack_kernel(const float* __restrict__ fw, const float* __restrict__ iw,
                            const float* __restrict__ uw, const float* __restrict__ ow,
                            const float* __restrict__ fb, const float* __restrict__ ib,
                            const float* __restrict__ ub, const float* __restrict__ ob)
{
    int idx = blockIdx.x * 256 + threadIdx.x;
    int row = idx >> 8;
    int k   = idx & 255;
    int gate = row >> 8;
    int rl   = row & 255;
    const float* w = (gate == 0) ? fw : (gate == 1) ? iw : (gate == 2) ? uw : ow;
    float vx = w[rl * (2 * H_) + k];
    __nv_bfloat16 h, l;
    split1(vx, h, l);
    g_Wxh[idx] = h; g_Wxl[idx] = l;
    g_Wh[idx]  = w[rl * (2 * H_) + H_ + k];
    if (idx < G4_) {
        int g2 = idx >> 8;
        const float* b = (g2 == 0) ? fb : (g2 == 1) ? ib : (g2 == 2) ? ub : ob;
        g_bias[idx] = b[idx & 255];
    }
}

// ================= bf16x3 mma.sync GEMM, cp.async 3-stage ===================
// C[M,N] = act(A[M,K] @ W[N,K]^T + bias), bf16x3 from hi/lo planes.
// CTA tile 128x128, 256 thr (8 warps, warp tile 32x64). K-chunk 32.
// stage smem: A row 128B = [hi e0..31 | lo e0..31] (XOR-16B swizzle) 16KB + B 16KB.
#define GSTG 32768

__device__ __forceinline__ void issue_chunk(
    uint32_t sdst,
    const __nv_bfloat16* Ah0, const __nv_bfloat16* Al0,
    const __nv_bfloat16* Wh0, const __nv_bfloat16* Wl0,
    int k0, int lrow, int half)
{
    int e0 = k0 + half * 16;
    int u0 = half * 2;
    uint32_t rb = lrow * 128;
    int sw = lrow & 7;
    cpa16(sdst + rb + (((u0    ) ^ sw) << 4), Ah0 + e0);
    cpa16(sdst + rb + (((u0 + 1) ^ sw) << 4), Ah0 + e0 + 8);
    cpa16(sdst + rb + (((u0 + 4) ^ sw) << 4), Al0 + e0);
    cpa16(sdst + rb + (((u0 + 5) ^ sw) << 4), Al0 + e0 + 8);
    cpa16(sdst + 16384 + rb + (((u0    ) ^ sw) << 4), Wh0 + e0);
    cpa16(sdst + 16384 + rb + (((u0 + 1) ^ sw) << 4), Wh0 + e0 + 8);
    cpa16(sdst + 16384 + rb + (((u0 + 4) ^ sw) << 4), Wl0 + e0);
    cpa16(sdst + 16384 + rb + (((u0 + 5) ^ sw) << 4), Wl0 + e0 + 8);
}

__global__ void __launch_bounds__(256, 2) gemm_mma(
    const __nv_bfloat16* __restrict__ Ah, const __nv_bfloat16* __restrict__ Al,
    const __nv_bfloat16* __restrict__ Whp, const __nv_bfloat16* __restrict__ Wlp,
    const float* __restrict__ bias, void* __restrict__ C0, void* __restrict__ C1,
    int K, int N, int act, int outpk)
{
    extern __shared__ char smc[];
    uint32_t sbase = smem_u32(smc);
    int tid = threadIdx.x, lane = tid & 31, wid = tid >> 5;
    int m0 = blockIdx.y * 128, n0 = blockIdx.x * 128;
    int wm = (wid >> 1) * 32, wn = (wid & 1) * 64;

    int q = lane >> 3, r = lane & 7;
    int rA0 = wm + (q & 1) * 8 + r;
    int cuA = q >> 1;
    int rBb = wn + (q >> 1) * 8 + r;
    int cuB = q & 1;

    int lrow = tid >> 1, half = tid & 1;
    const __nv_bfloat16* Ah0 = Ah  + (size_t)(m0 + lrow) * K;
    const __nv_bfloat16* Al0 = Al  + (size_t)(m0 + lrow) * K;
    const __nv_bfloat16* Wh0 = Whp + (size_t)(n0 + lrow) * K;
    const __nv_bfloat16* Wl0 = Wlp + (size_t)(n0 + lrow) * K;

    float c[2][8][4];
#pragma unroll
    for (int mt = 0; mt < 2; mt++)
#pragma unroll
        for (int f = 0; f < 8; f++)
#pragma unroll
            for (int e = 0; e < 4; e++) c[mt][f][e] = 0.f;

    int nc = K >> 5;

    issue_chunk(sbase, Ah0, Al0, Wh0, Wl0, 0, lrow, half);
    CP_COMMIT();
    issue_chunk(sbase + GSTG, Ah0, Al0, Wh0, Wl0, 32, lrow, half);
    CP_COMMIT();

    int sidx = 0;
#pragma unroll 1
    for (int ch = 0; ch < nc; ch++) {
        if (ch + 1 < nc) CP_WAIT1(); else CP_WAIT0();
        __syncthreads();
        if (ch + 2 < nc) {
            int s2 = sidx + 2; if (s2 >= 3) s2 -= 3;
            issue_chunk(sbase + s2 * GSTG, Ah0, Al0, Wh0, Wl0,
                        (ch + 2) * 32, lrow, half);
            CP_COMMIT();
        }
        uint32_t st = sbase + sidx * GSTG;
#pragma unroll
        for (int kk = 0; kk < 2; kk++) {
            uint32_t ah[2][4], al[2][4], bh[8][2], bl[8][2];
#pragma unroll
            for (int mt = 0; mt < 2; mt++) {
                int row = rA0 + mt * 16;
                ldsm4(ah[mt], st + row * 128 + (((cuA + kk * 2    ) ^ (row & 7)) << 4));
                ldsm4(al[mt], st + row * 128 + (((cuA + kk * 2 + 4) ^ (row & 7)) << 4));
            }
#pragma unroll
            for (int nt = 0; nt < 4; nt++) {
                int row = rBb + nt * 16;
                uint32_t t4[4];
                ldsm4(t4, st + 16384 + row * 128 + (((cuB + kk * 2    ) ^ (row & 7)) << 4));
                bh[nt * 2][0] = t4[0]; bh[nt * 2][1] = t4[1];
                bh[nt * 2 + 1][0] = t4[2]; bh[nt * 2 + 1][1] = t4[3];
                ldsm4(t4, st + 16384 + row * 128 + (((cuB + kk * 2 + 4) ^ (row & 7)) << 4));
                bl[nt * 2][0] = t4[0]; bl[nt * 2][1] = t4[1];
                bl[nt * 2 + 1][0] = t4[2]; bl[nt * 2 + 1][1] = t4[3];
            }
#pragma unroll
            for (int mt = 0; mt < 2; mt++)
#pragma unroll
                for (int f = 0; f < 8; f++) {
                    mma_bf16(c[mt][f], ah[mt], bh[f]);
                    mma_bf16(c[mt][f], ah[mt], bl[f]);
                    mma_bf16(c[mt][f], al[mt], bh[f]);
                }
        }
        __syncthreads();
        sidx++; if (sidx >= 3) sidx = 0;
    }

    // epilogue
#pragma unroll
    for (int mt = 0; mt < 2; mt++) {
        int row = m0 + wm + mt * 16 + (lane >> 2);
#pragma unroll
        for (int f = 0; f < 8; f++) {
            int col = n0 + wn + f * 8 + (lane & 3) * 2;
            float b0 = __ldg(&bias[col]), b1 = __ldg(&bias[col + 1]);
            float v0 = c[mt][f][0] + b0, v1 = c[mt][f][1] + b1;
            float v2 = c[mt][f][2] + b0, v3 = c[mt][f][3] + b1;
            if (act == 1) {
                v0 = tanhf(v0); v1 = tanhf(v1); v2 = tanhf(v2); v3 = tanhf(v3);
            } else if (act == 2) {
                v0 = fmaxf(v0, 0.f); v1 = fmaxf(v1, 0.f);
                v2 = fmaxf(v2, 0.f); v3 = fmaxf(v3, 0.f);
            }
            if (outpk) {
                __nv_bfloat16* Ch = (__nv_bfloat16*)C0;
                __nv_bfloat16* Cl = (__nv_bfloat16*)C1;
                __nv_bfloat16 h0, h1, h2, h3, l0, l1, l2, l3;
                split1(v0, h0, l0); split1(v1, h1, l1);
                split1(v2, h2, l2); split1(v3, h3, l3);
                *(__nv_bfloat162*)&Ch[(size_t)row * N + col] = __halves2bfloat162(h0, h1);
                *(__nv_bfloat162*)&Cl[(size_t)row * N + col] = __halves2bfloat162(l0, l1);
                *(__nv_bfloat162*)&Ch[(size_t)(row + 8) * N + col] = __halves2bfloat162(h2, h3);
                *(__nv_bfloat162*)&Cl[(size_t)(row + 8) * N + col] = __halves2bfloat162(l2, l3);
            } else {
                float* Cf = (float*)C0;
                *(float2*)&Cf[(size_t)row * N + col] = make_float2(v0, v1);
                *(float2*)&Cf[(size_t)(row + 8) * N + col] = make_float2(v2, v3);
            }
        }
    }
}

// ---------------- recurrence: cluster(8) + DSMEM all-gather -----------------
__device__ __forceinline__ float sigmoidf_(float x) {
    return 1.f / (1.f + expf(-x));
}

// 128 CTAs, clusters of 8. cta = bs*8 + cs; cluster = one bs (8 batch rows),
// rank cs owns hidden cols [32*cs, 32*cs+32). Wh register-resident (FFMA2).
// hx lives in every CTA's smem [2][8*256]; publish via st.shared::cluster to
// all 8 ranks; one barrier.cluster per step.
__global__ void __cluster_dims__(8, 1, 1) __launch_bounds__(256, 1) recur_kernel()
{
    __shared__ float hx_sm[2][8 * 256];
    __shared__ float red[2 * 128 * 9];

    int tid = threadIdx.x;
    int cta = blockIdx.x;
    int bs = cta >> 3, cs = cta & 7;

    // GEMM role: register-resident Wh row-half as packed f32 pairs
    int r  = tid & 127;
    int kh = tid >> 7;
    int gg = r >> 5, jl = r & 31;
    int R = gg * H_ + cs * 32 + jl;
    unsigned long long wreg2[64];
    {
        const ulonglong2* wp = (const ulonglong2*)&g_Wh[(size_t)R * H_ + kh * 128];
#pragma unroll
        for (int qq = 0; qq < 32; qq++) {
            ulonglong2 v = wp[qq];
            wreg2[2 * qq] = v.x; wreg2[2 * qq + 1] = v.y;
        }
    }

    int b    = tid >> 5;
    int lane = tid & 31;
    int bidx = bs * 8 + b;
    int col  = cs * 32 + lane;
    float cx = 0.f;

    // zero step-0 hx buffer
#pragma unroll
    for (int i = 0; i < 8; i++) hx_sm[0][tid + i * 256] = 0.f;
    uint32_t pub_addr[2];
    pub_addr[0] = smem_u32(&hx_sm[0][b * 256 + col]);
    pub_addr[1] = smem_u32(&hx_sm[1][b * 256 + col]);
    __syncthreads();
    CLUSTER_SYNC();

    for (int t = 0; t < T_; t++) {
        int cur = t & 1, nxt = cur ^ 1;

        // prefetch precomputed gate inputs (independent of hx)
        const float* gxrow = &g_gx[((size_t)t * B_ + bidx) * G4_ + col];
        float gx0 = __ldg(&gxrow[0]);
        float gx1 = __ldg(&gxrow[256]);
        float gx2 = __ldg(&gxrow[512]);
        float gx3 = __ldg(&gxrow[768]);

        // hx @ Wh^T partial via packed dual-FMA (k-split accumulators)
        unsigned long long acc2[8];
#pragma unroll
        for (int bb = 0; bb < 8; bb++) acc2[bb] = 0ULL;
        const ulonglong2* hb2 = (const ulonglong2*)(&hx_sm[cur][0] + kh * 128);
#pragma unroll
        for (int qq = 0; qq < 32; qq++) {
#pragma unroll
            for (int bb = 0; bb < 8; bb++) {
                ulonglong2 hv = hb2[bb * 64 + qq];
                fma2(acc2[bb], wreg2[2 * qq],     hv.x);
                fma2(acc2[bb], wreg2[2 * qq + 1], hv.y);
            }
        }
#pragma unroll
        for (int bb = 0; bb < 8; bb++) {
            unsigned long long a = acc2[bb];
            float alo = __uint_as_float((uint32_t)a);
            float ahi = __uint_as_float((uint32_t)(a >> 32));
            red[(kh * 128 + r) * 9 + bb] = alo + ahi;
        }
        __syncthreads();

        float s0 = red[(0 * 32 + lane) * 9 + b] + red[(128 + 0 * 32 + lane) * 9 + b];
        float s1 = red[(1 * 32 + lane) * 9 + b] + red[(128 + 1 * 32 + lane) * 9 + b];
        float s2 = red[(2 * 32 + lane) * 9 + b] + red[(128 + 2 * 32 + lane) * 9 + b];
        float s3 = red[(3 * 32 + lane) * 9 + b] + red[(128 + 3 * 32 + lane) * 9 + b];

        float fg = sigmoidf_(s0 + gx0);
        float ig = sigmoidf_(s1 + gx1);
        float ug = tanhf(s2 + gx2);
        float og = sigmoidf_(s3 + gx3);
        cx = fg * cx + ig * ug;
        float h = og * tanhf(cx);

        // publish h into all 8 cluster CTAs' next-step buffers
#pragma unroll
        for (int rk = 0; rk < 8; rk++)
            st_cluster_f32(pub_addr[nxt], (uint32_t)rk, h);

        // stream hs out as hi/lo planes for the classifier GEMM
        size_t oidx = ((size_t)t * B_ + bidx) * H_ + col;
        __nv_bfloat16 hh, hl;
        split1(h, hh, hl);
        g_hsh[oidx] = hh;
        g_hsl[oidx] = hl;

        CLUSTER_SYNC();
    }
}

// ---------------- final tiny projection to 2 logits ------------------------
__global__ void __launch_bounds__(256) final_kernel(
    const float* __restrict__ z, const float* __restrict__ w2,
    const float* __restrict__ b2, float* __restrict__ out)
{
    __shared__ float w[512];
    __shared__ float bb[2];
    int tid = threadIdx.x;
    w[tid] = w2[tid];
    w[tid + 256] = w2[tid + 256];
    if (tid < 2) bb[tid] = b2[tid];
    __syncthreads();

    int row = blockIdx.x * 256 + tid;
    const float4* zp = (const float4*)&z[(size_t)row * H_];
    float a0 = 0.f, a1 = 0.f;
#pragma unroll
    for (int qq = 0; qq < 64; qq++) {
        float4 v = zp[qq];
        a0 = fmaf(v.x, w[4 * qq + 0], a0);
        a0 = fmaf(v.y, w[4 * qq + 1], a0);
        a0 = fmaf(v.z, w[4 * qq + 2], a0);
        a0 = fmaf(v.w, w[4 * qq + 3], a0);
        a1 = fmaf(v.x, w[256 + 4 * qq + 0], a1);
        a1 = fmaf(v.y, w[256 + 4 * qq + 1], a1);
        a1 = fmaf(v.z, w[256 + 4 * qq + 2], a1);
        a1 = fmaf(v.w, w[256 + 4 * qq + 3], a1);
    }
    out[row * 2 + 0] = a0 + bb[0];
    out[row * 2 + 1] = a1 + bb[1];
}

// ---------------- host -----------------------------------------------------
extern "C" void kernel_launch(void* const* d_in, const int* in_sizes, int n_in,
                              void* d_out, int out_size)
{
    const float* x    = (const float*)d_in[0];
    const float* fc_w = (const float*)d_in[1];
    const float* fc_b = (const float*)d_in[2];
    const float* fw   = (const float*)d_in[3];
    const float* fb   = (const float*)d_in[4];
    const float* iw   = (const float*)d_in[5];
    const float* ib   = (const float*)d_in[6];
    const float* uw   = (const float*)d_in[7];
    const float* ub   = (const float*)d_in[8];
    const float* ow   = (const float*)d_in[9];
    const float* ob   = (const float*)d_in[10];
    const float* w0   = (const float*)d_in[11];
    const float* b0   = (const float*)d_in[12];
    const float* w1   = (const float*)d_in[13];
    const float* b1   = (const float*)d_in[14];
    const float* w2   = (const float*)d_in[15];
    const float* b2   = (const float*)d_in[16];
    float* out = (float*)d_out;

    void *p_xh, *p_xl, *p_hh, *p_hl, *p_gx, *p_hsh, *p_hsl;
    void *p_z0h, *p_z0l, *p_z1, *p_fwh, *p_fwl, *p_wxh, *p_wxl, *p_bias;
    void *p_w0h, *p_w0l, *p_w1h, *p_w1l;
    cudaGetSymbolAddress(&p_xh,  g_xh);
    cudaGetSymbolAddress(&p_xl,  g_xl);
    cudaGetSymbolAddress(&p_hh,  g_hh);
    cudaGetSymbolAddress(&p_hl,  g_hl);
    cudaGetSymbolAddress(&p_gx,  g_gx);
    cudaGetSymbolAddress(&p_hsh, g_hsh);
    cudaGetSymbolAddress(&p_hsl, g_hsl);
    cudaGetSymbolAddress(&p_z0h, g_z0h);
    cudaGetSymbolAddress(&p_z0l, g_z0l);
    cudaGetSymbolAddress(&p_z1,  g_z1);
    cudaGetSymbolAddress(&p_fwh, g_fwh);
    cudaGetSymbolAddress(&p_fwl, g_fwl);
    cudaGetSymbolAddress(&p_wxh, g_Wxh);
    cudaGetSymbolAddress(&p_wxl, g_Wxl);
    cudaGetSymbolAddress(&p_bias, g_bias);
    cudaGetSymbolAddress(&p_w0h, g_w0h);
    cudaGetSymbolAddress(&p_w0l, g_w0l);
    cudaGetSymbolAddress(&p_w1h, g_w1h);
    cudaGetSymbolAddress(&p_w1l, g_w1l);

    cudaFuncSetAttribute(gemm_mma, cudaFuncAttributeMaxDynamicSharedMemorySize,
                         3 * GSTG);

    // split-pack operands into bf16 hi/lo planes
    splitpack_kernel<<<(TB_ * D_ / 4) / 256, 256>>>(
        x, (__nv_bfloat16*)p_xh, (__nv_bfloat16*)p_xl, TB_ * D_ / 4);
    splitpack_kernel<<<(H_ * D_ / 4 + 255) / 256, 256>>>(
        fc_w, (__nv_bfloat16*)p_fwh, (__nv_bfloat16*)p_fwl, H_ * D_ / 4);
    splitpack_kernel<<<(H_ * H_ / 4 + 255) / 256, 256>>>(
        w0, (__nv_bfloat16*)p_w0h, (__nv_bfloat16*)p_w0l, H_ * H_ / 4);
    splitpack_kernel<<<(H_ * H_ / 4 + 255) / 256, 256>>>(
        w1, (__nv_bfloat16*)p_w1h, (__nv_bfloat16*)p_w1l, H_ * H_ / 4);
    pack_kernel<<<(G4_ * H_) / 256, 256>>>(fw, iw, uw, ow, fb, ib, ub, ob);

    // h = tanh(x @ fc_w^T + fc_b)   [TB,512] -> [TB,256] hi/lo planes
    gemm_mma<<<dim3(H_ / 128, TB_ / 128), 256, 3 * GSTG>>>(
        (const __nv_bfloat16*)p_xh, (const __nv_bfloat16*)p_xl,
        (const __nv_bfloat16*)p_fwh, (const __nv_bfloat16*)p_fwl,
        fc_b, p_hh, p_hl, D_, H_, 1, 1);

    // gx = h @ Wx^T + bias          [TB,256] -> [TB,1024] f32
    gemm_mma<<<dim3(G4_ / 128, TB_ / 128), 256, 3 * GSTG>>>(
        (const __nv_bfloat16*)p_hh, (const __nv_bfloat16*)p_hl,
        (const __nv_bfloat16*)p_wxh, (const __nv_bfloat16*)p_wxl,
        (const float*)p_bias, p_gx, 0, H_, G4_, 0, 0);

    // LSTM recurrence (persistent, cluster-synchronized)
    recur_kernel<<<128, 256>>>();

    // classifier
    gemm_mma<<<dim3(H_ / 128, TB_ / 128), 256, 3 * GSTG>>>(
        (const __nv_bfloat16*)p_hsh, (const __nv_bfloat16*)p_hsl,
        (const __nv_bfloat16*)p_w0h, (const __nv_bfloat16*)p_w0l,
        b0, p_z0h, p_z0l, H_, H_, 2, 1);
    gemm_mma<<<dim3(H_ / 128, TB_ / 128), 256, 3 * GSTG>>>(
        (const __nv_bfloat16*)p_z0h, (const __nv_bfloat16*)p_z0l,
        (const __nv_bfloat16*)p_w1h, (const __nv_bfloat16*)p_w1l,
        b1, p_z1, 0, H_, H_, 2, 0);
    final_kernel<<<TB_ / 256, 256>>>((const float*)p_z1, w2, b2, out);
}

// round 7
// speedup vs baseline: 1.2291x; 1.2291x over previous
#include <cuda_runtime.h>
#include <cuda_bf16.h>
#include <math.h>
#include <stdint.h>

#define T_  1024
#define B_  128
#define D_  512
#define H_  256
#define TB_ (T_ * B_)      // 131072
#define G4_ (4 * H_)       // 1024

// ---------------- scratch (device globals; no cudaMalloc allowed) ----------
__device__ uint32_t g_xp [(size_t)TB_ * D_];   // x split-packed (hi<<16|lo)
__device__ uint32_t g_hb [(size_t)TB_ * H_];   // tanh(fc) packed
__device__ float    g_gx [(size_t)TB_ * G4_];  // gate inputs (f32, recur reads)
__device__ uint32_t g_hsb[(size_t)TB_ * H_];   // recurrence out packed
__device__ uint32_t g_z0b[(size_t)TB_ * H_];   // classifier tmp packed
__device__ float    g_z1 [(size_t)TB_ * H_];   // classifier tmp f32
__device__ uint32_t g_Wxp[G4_ * H_];           // packed input weights (f,i,u,o)
__device__ float    g_Wh [G4_ * H_];           // recurrent weights f32
__device__ float    g_bias[G4_];               // packed biases
__device__ uint32_t g_fcwp[H_ * D_];
__device__ uint32_t g_w0p[H_ * H_];
__device__ uint32_t g_w1p[H_ * H_];
__device__ float    g_hx[2 * B_ * H_];         // double-buffered hidden state
__device__ unsigned g_bar_in [16 * 32];        // per-group barrier (128B padded)
__device__ unsigned g_bar_gen[16 * 32];

// ================= helpers ==================================================
__device__ __forceinline__ uint32_t smem_u32(const void* p) {
    uint32_t a;
    asm("{ .reg .u64 t; cvta.to.shared.u64 t, %1; cvt.u32.u64 %0, t; }"
        : "=r"(a) : "l"(p));
    return a;
}

__device__ __forceinline__ void mma_bf16(float* c, const uint32_t* a,
                                         const uint32_t* b) {
    asm volatile(
        "mma.sync.aligned.m16n8k16.row.col.f32.bf16.bf16.f32 "
        "{%0,%1,%2,%3}, {%4,%5,%6,%7}, {%8,%9}, {%0,%1,%2,%3};"
        : "+f"(c[0]), "+f"(c[1]), "+f"(c[2]), "+f"(c[3])
        : "r"(a[0]), "r"(a[1]), "r"(a[2]), "r"(a[3]), "r"(b[0]), "r"(b[1]));
}

__device__ __forceinline__ void ldsm4(uint32_t* d, uint32_t addr) {
    asm volatile("ldmatrix.sync.aligned.m8n8.x4.shared.b16 {%0,%1,%2,%3}, [%4];"
        : "=r"(d[0]), "=r"(d[1]), "=r"(d[2]), "=r"(d[3]) : "r"(addr));
}

// split-pack one float: (bf16_hi << 16) | bf16_lo
__device__ __forceinline__ uint32_t pk(float v) {
    __nv_bfloat16 h = __float2bfloat16_rn(v);
    float hf = __bfloat162float(h);
    __nv_bfloat16 l = __float2bfloat16_rn(v - hf);
    return ((uint32_t)__bfloat16_as_ushort(h) << 16) | __bfloat16_as_ushort(l);
}

// packed dual fp32 FMA (SASS FFMA2)
__device__ __forceinline__ void fma2(unsigned long long& d,
                                     unsigned long long a,
                                     unsigned long long b) {
    asm("fma.rn.f32x2 %0, %1, %2, %0;" : "+l"(d) : "l"(a), "l"(b));
}

// ---------------- generic f32 -> packed splitter ---------------------------
__global__ void splitpack_kernel(const float* __restrict__ s,
                                 uint32_t* __restrict__ d, int n4) {
    int i = blockIdx.x * 256 + threadIdx.x;
    if (i < n4) {
        float4 v = ((const float4*)s)[i];
        uint4 o;
        o.x = pk(v.x); o.y = pk(v.y); o.z = pk(v.z); o.w = pk(v.w);
        ((uint4*)d)[i] = o;
    }
}

// ---------------- pack gate weights: rows [f|i|u|o], split x/h halves ------
__global__ void pack_kernel(const float* __restrict__ fw, const float* __restrict__ iw,
                            const float* __restrict__ uw, const float* __restrict__ ow,
                            const float* __restrict__ fb, const float* __restrict__ ib,
                            const float* __restrict__ ub, const float* __restrict__ ob)
{
    int idx = blockIdx.x * 256 + threadIdx.x;
    int row = idx >> 8;
    int k   = idx & 255;
    int gate = row >> 8;
    int rl   = row & 255;
    const float* w = (gate == 0) ? fw : (gate == 1) ? iw : (gate == 2) ? uw : ow;
    g_Wxp[idx] = pk(w[rl * (2 * H_) + k]);
    g_Wh[idx]  = w[rl * (2 * H_) + H_ + k];
    if (idx < G4_) {
        int g2 = idx >> 8;
        const float* b = (g2 == 0) ? fb : (g2 == 1) ? ib : (g2 == 2) ? ub : ob;
        g_bias[idx] = b[idx & 255];
    }
}

// ================= bf16x3 mma.sync GEMM, occupancy 2 ========================
// C[M,N] = act(A[M,K] @ W[N,K]^T + bias). A/W u32 packed (hi<<16|lo).
// CTA tile 128x64, 256 thr (8 warps = 4M x 2N, warp tile 32x32). K-chunk 32.
// stage smem: A 16KB + B 8KB = 24KB; double buffered = 48KB; 2 CTAs/SM.
#define ASTG 16384
#define STAGE_BYTES 24576

__global__ void __launch_bounds__(256, 2) gemm_mma(
    const uint32_t* __restrict__ A, const uint32_t* __restrict__ W,
    const float* __restrict__ bias, void* __restrict__ Cv,
    int K, int N, int act, int outpk)
{
    extern __shared__ char smc[];
    uint32_t sbase = smem_u32(smc);
    int tid = threadIdx.x, lane = tid & 31, wid = tid >> 5;
    int m0 = blockIdx.y * 128, n0 = blockIdx.x * 64;
    int wm = (wid >> 1) * 32, wn = (wid & 1) * 32;

    // lane decode for ldmatrix addressing
    int q = lane >> 3, r = lane & 7;
    int rA0 = wm + (q & 1) * 8 + r;          // A frag rows (mt adds 16)
    int cuA = q >> 1;
    int rBb = wn + (q >> 1) * 8 + r;         // B frag rows (nt adds 16)
    int cuB = q & 1;

    // global loads: A 2 thr/row x 16 elems (4 uint4); B 4 thr/row x 8 (2 uint4)
    int larow = tid >> 1, laseg = (tid & 1) * 16;
    int lbrow = tid >> 2, lbseg = (tid & 3) * 8;
    const uint32_t* Ag = A + (size_t)(m0 + larow) * K + laseg;
    const uint32_t* Wg = W + (size_t)(n0 + lbrow) * K + lbseg;
    uint32_t sha[4], sla[4], shb[2], slb[2];
#pragma unroll
    for (int j = 0; j < 4; j++) {
        int col = laseg + 4 * j;
        int unit = col >> 3;
        int off = (col & 4) * 2;
        sha[j] = larow * 128 + (((unit    ) ^ (larow & 7)) << 4) + off;
        sla[j] = larow * 128 + (((unit + 4) ^ (larow & 7)) << 4) + off;
    }
#pragma unroll
    for (int j = 0; j < 2; j++) {
        int col = lbseg + 4 * j;
        int unit = col >> 3;
        int off = (col & 4) * 2;
        shb[j] = ASTG + lbrow * 128 + (((unit    ) ^ (lbrow & 7)) << 4) + off;
        slb[j] = ASTG + lbrow * 128 + (((unit + 4) ^ (lbrow & 7)) << 4) + off;
    }

    float c[2][4][4];
#pragma unroll
    for (int mt = 0; mt < 2; mt++)
#pragma unroll
        for (int f = 0; f < 4; f++)
#pragma unroll
            for (int e = 0; e < 4; e++) c[mt][f][e] = 0.f;

    int nc = K >> 5;

    // prologue: chunk 0 -> stage 0
    {
        char* st = smc;
#pragma unroll
        for (int j = 0; j < 4; j++) {
            uint4 v = *(const uint4*)&Ag[4 * j];
            uint2 hi, lo;
            hi.x = __byte_perm(v.x, v.y, 0x7632);
            lo.x = __byte_perm(v.x, v.y, 0x5410);
            hi.y = __byte_perm(v.z, v.w, 0x7632);
            lo.y = __byte_perm(v.z, v.w, 0x5410);
            *(uint2*)(st + sha[j]) = hi;
            *(uint2*)(st + sla[j]) = lo;
        }
#pragma unroll
        for (int j = 0; j < 2; j++) {
            uint4 v = *(const uint4*)&Wg[4 * j];
            uint2 hi, lo;
            hi.x = __byte_perm(v.x, v.y, 0x7632);
            lo.x = __byte_perm(v.x, v.y, 0x5410);
            hi.y = __byte_perm(v.z, v.w, 0x7632);
            lo.y = __byte_perm(v.z, v.w, 0x5410);
            *(uint2*)(st + shb[j]) = hi;
            *(uint2*)(st + slb[j]) = lo;
        }
    }
    __syncthreads();

#pragma unroll 1
    for (int ch = 0; ch < nc; ch++) {
        // prefetch next chunk into registers
        uint4 va[4], vb[2];
        if (ch + 1 < nc) {
            const uint32_t* Ap = Ag + (ch + 1) * 32;
            const uint32_t* Wp = Wg + (ch + 1) * 32;
#pragma unroll
            for (int j = 0; j < 4; j++) va[j] = *(const uint4*)&Ap[4 * j];
#pragma unroll
            for (int j = 0; j < 2; j++) vb[j] = *(const uint4*)&Wp[4 * j];
        }

        uint32_t st = sbase + (ch & 1) * STAGE_BYTES;
#pragma unroll
        for (int kk = 0; kk < 2; kk++) {
            uint32_t ah[2][4], al[2][4], bh[4][2], bl[4][2];
#pragma unroll
            for (int mt = 0; mt < 2; mt++) {
                int row = rA0 + mt * 16;
                ldsm4(ah[mt], st + row * 128 + (((cuA + kk * 2    ) ^ (row & 7)) << 4));
                ldsm4(al[mt], st + row * 128 + (((cuA + kk * 2 + 4) ^ (row & 7)) << 4));
            }
#pragma unroll
            for (int nt = 0; nt < 2; nt++) {
                int row = rBb + nt * 16;
                uint32_t t4[4];
                ldsm4(t4, st + ASTG + row * 128 + (((cuB + kk * 2    ) ^ (row & 7)) << 4));
                bh[nt * 2][0] = t4[0]; bh[nt * 2][1] = t4[1];
                bh[nt * 2 + 1][0] = t4[2]; bh[nt * 2 + 1][1] = t4[3];
                ldsm4(t4, st + ASTG + row * 128 + (((cuB + kk * 2 + 4) ^ (row & 7)) << 4));
                bl[nt * 2][0] = t4[0]; bl[nt * 2][1] = t4[1];
                bl[nt * 2 + 1][0] = t4[2]; bl[nt * 2 + 1][1] = t4[3];
            }
#pragma unroll
            for (int mt = 0; mt < 2; mt++)
#pragma unroll
                for (int f = 0; f < 4; f++) {
                    mma_bf16(c[mt][f], ah[mt], bh[f]);
                    mma_bf16(c[mt][f], ah[mt], bl[f]);
                    mma_bf16(c[mt][f], al[mt], bh[f]);
                }
        }

        if (ch + 1 < nc) {
            char* stw = smc + ((ch + 1) & 1) * STAGE_BYTES;
#pragma unroll
            for (int j = 0; j < 4; j++) {
                uint2 hi, lo;
                hi.x = __byte_perm(va[j].x, va[j].y, 0x7632);
                lo.x = __byte_perm(va[j].x, va[j].y, 0x5410);
                hi.y = __byte_perm(va[j].z, va[j].w, 0x7632);
                lo.y = __byte_perm(va[j].z, va[j].w, 0x5410);
                *(uint2*)(stw + sha[j]) = hi;
                *(uint2*)(stw + sla[j]) = lo;
            }
#pragma unroll
            for (int j = 0; j < 2; j++) {
                uint2 hi, lo;
                hi.x = __byte_perm(vb[j].x, vb[j].y, 0x7632);
                lo.x = __byte_perm(vb[j].x, vb[j].y, 0x5410);
                hi.y = __byte_perm(vb[j].z, vb[j].w, 0x7632);
                lo.y = __byte_perm(vb[j].z, vb[j].w, 0x5410);
                *(uint2*)(stw + shb[j]) = hi;
                *(uint2*)(stw + slb[j]) = lo;
            }
            __syncthreads();
        }
    }

    // epilogue: bias + activation straight from fragments
#pragma unroll
    for (int mt = 0; mt < 2; mt++) {
        int row = m0 + wm + mt * 16 + (lane >> 2);
#pragma unroll
        for (int f = 0; f < 4; f++) {
            int col = n0 + wn + f * 8 + (lane & 3) * 2;
            float b0 = __ldg(&bias[col]), b1 = __ldg(&bias[col + 1]);
            float v0 = c[mt][f][0] + b0, v1 = c[mt][f][1] + b1;
            float v2 = c[mt][f][2] + b0, v3 = c[mt][f][3] + b1;
            if (act == 1) {
                v0 = tanhf(v0); v1 = tanhf(v1); v2 = tanhf(v2); v3 = tanhf(v3);
            } else if (act == 2) {
                v0 = fmaxf(v0, 0.f); v1 = fmaxf(v1, 0.f);
                v2 = fmaxf(v2, 0.f); v3 = fmaxf(v3, 0.f);
            }
            if (outpk) {
                uint32_t* Cp = (uint32_t*)Cv;
                uint2 p01; p01.x = pk(v0); p01.y = pk(v1);
                uint2 p23; p23.x = pk(v2); p23.y = pk(v3);
                *(uint2*)&Cp[(size_t)row * N + col] = p01;
                *(uint2*)&Cp[(size_t)(row + 8) * N + col] = p23;
            } else {
                float* Cf = (float*)Cv;
                *(float2*)&Cf[(size_t)row * N + col] = make_float2(v0, v1);
                *(float2*)&Cf[(size_t)(row + 8) * N + col] = make_float2(v2, v3);
            }
        }
    }
}

// ---------------- recurrence -----------------------------------------------
__device__ __forceinline__ float sigmoidf_(float x) {
    return 1.f / (1.f + expf(-x));
}

// barrier over the 8 CTAs of one batch group (grp = bs). Counters padded to
// 128B so the 16 groups never share an L2 sector.
__device__ __forceinline__ void group_barrier(int grp, unsigned* s_gen_p) {
    __syncthreads();
    if (threadIdx.x == 0) {
        unsigned my = *s_gen_p;
        __threadfence();
        unsigned t = atomicAdd(&g_bar_in[grp * 32], 1u);
        if (t == 7u) {
            g_bar_in[grp * 32] = 0;
            __threadfence();
            atomicAdd(&g_bar_gen[grp * 32], 1u);
        } else {
            while (*(volatile unsigned*)&g_bar_gen[grp * 32] == my) { }
        }
        *s_gen_p = my + 1;
    }
    __syncthreads();
}

__global__ void __launch_bounds__(256, 1) recur_kernel()
{
    __shared__ float hx_sm[8 * 256];
    __shared__ float red[2 * 128 * 9];
    __shared__ unsigned s_gen;

    int tid = threadIdx.x;
    int cta = blockIdx.x;
    int bs = cta >> 3, cs = cta & 7;

    // GEMM role: register-resident Wh row-half as packed f32 pairs
    int r  = tid & 127;
    int kh = tid >> 7;
    int gg = r >> 5, jl = r & 31;
    int R = gg * H_ + cs * 32 + jl;
    unsigned long long wreg2[64];
    {
        const ulonglong2* wp = (const ulonglong2*)&g_Wh[(size_t)R * H_ + kh * 128];
#pragma unroll
        for (int qq = 0; qq < 32; qq++) {
            ulonglong2 v = wp[qq];
            wreg2[2 * qq] = v.x; wreg2[2 * qq + 1] = v.y;
        }
    }

    int b    = tid >> 5;
    int lane = tid & 31;
    int bidx = bs * 8 + b;
    int col  = cs * 32 + lane;
    float cx = 0.f;

    g_hx[bidx * H_ + col] = 0.f;
    if (tid == 0) s_gen = *(volatile unsigned*)&g_bar_gen[bs * 32];
    group_barrier(bs, &s_gen);

    for (int t = 0; t < T_; t++) {
        int cur = t & 1, nxt = cur ^ 1;

        const float* gxrow = &g_gx[((size_t)t * B_ + bidx) * G4_ + col];
        float gx0 = __ldg(&gxrow[0]);
        float gx1 = __ldg(&gxrow[256]);
        float gx2 = __ldg(&gxrow[512]);
        float gx3 = __ldg(&gxrow[768]);

        {
            const float4* src = (const float4*)&g_hx[cur * (B_ * H_) + bs * 8 * H_];
            float4* dst = (float4*)hx_sm;
            dst[tid]       = __ldcg(&src[tid]);
            dst[tid + 256] = __ldcg(&src[tid + 256]);
        }
        __syncthreads();

        // hx @ Wh^T partial via packed dual-FMA (k-split accumulators)
        unsigned long long acc2[8];
#pragma unroll
        for (int bb = 0; bb < 8; bb++) acc2[bb] = 0ULL;
        const ulonglong2* hb2 = (const ulonglong2*)(hx_sm + kh * 128);
#pragma unroll
        for (int qq = 0; qq < 32; qq++) {
#pragma unroll
            for (int bb = 0; bb < 8; bb++) {
                ulonglong2 hv = hb2[bb * 64 + qq];
                fma2(acc2[bb], wreg2[2 * qq],     hv.x);
                fma2(acc2[bb], wreg2[2 * qq + 1], hv.y);
            }
        }
#pragma unroll
        for (int bb = 0; bb < 8; bb++) {
            unsigned long long a = acc2[bb];
            float alo = __uint_as_float((uint32_t)a);
            float ahi = __uint_as_float((uint32_t)(a >> 32));
            red[(kh * 128 + r) * 9 + bb] = alo + ahi;
        }
        __syncthreads();

        float s0 = red[(0 * 32 + lane) * 9 + b] + red[(128 + 0 * 32 + lane) * 9 + b];
        float s1 = red[(1 * 32 + lane) * 9 + b] + red[(128 + 1 * 32 + lane) * 9 + b];
        float s2 = red[(2 * 32 + lane) * 9 + b] + red[(128 + 2 * 32 + lane) * 9 + b];
        float s3 = red[(3 * 32 + lane) * 9 + b] + red[(128 + 3 * 32 + lane) * 9 + b];

        float fg = sigmoidf_(s0 + gx0);
        float ig = sigmoidf_(s1 + gx1);
        float ug = tanhf(s2 + gx2);
        float og = sigmoidf_(s3 + gx3);
        cx = fg * cx + ig * ug;
        float h = og * tanhf(cx);

        g_hx[nxt * (B_ * H_) + bidx * H_ + col] = h;
        g_hsb[((size_t)t * B_ + bidx) * H_ + col] = pk(h);

        group_barrier(bs, &s_gen);
    }
}

// ---------------- final tiny projection to 2 logits ------------------------
__global__ void __launch_bounds__(256) final_kernel(
    const float* __restrict__ z, const float* __restrict__ w2,
    const float* __restrict__ b2, float* __restrict__ out)
{
    __shared__ float w[512];
    __shared__ float bb[2];
    int tid = threadIdx.x;
    w[tid] = w2[tid];
    w[tid + 256] = w2[tid + 256];
    if (tid < 2) bb[tid] = b2[tid];
    __syncthreads();

    int row = blockIdx.x * 256 + tid;
    const float4* zp = (const float4*)&z[(size_t)row * H_];
    float a0 = 0.f, a1 = 0.f;
#pragma unroll
    for (int qq = 0; qq < 64; qq++) {
        float4 v = zp[qq];
        a0 = fmaf(v.x, w[4 * qq + 0], a0);
        a0 = fmaf(v.y, w[4 * qq + 1], a0);
        a0 = fmaf(v.z, w[4 * qq + 2], a0);
        a0 = fmaf(v.w, w[4 * qq + 3], a0);
        a1 = fmaf(v.x, w[256 + 4 * qq + 0], a1);
        a1 = fmaf(v.y, w[256 + 4 * qq + 1], a1);
        a1 = fmaf(v.z, w[256 + 4 * qq + 2], a1);
        a1 = fmaf(v.w, w[256 + 4 * qq + 3], a1);
    }
    out[row * 2 + 0] = a0 + bb[0];
    out[row * 2 + 1] = a1 + bb[1];
}

// ---------------- host -----------------------------------------------------
extern "C" void kernel_launch(void* const* d_in, const int* in_sizes, int n_in,
                              void* d_out, int out_size)
{
    const float* x    = (const float*)d_in[0];
    const float* fc_w = (const float*)d_in[1];
    const float* fc_b = (const float*)d_in[2];
    const float* fw   = (const float*)d_in[3];
    const float* fb   = (const float*)d_in[4];
    const float* iw   = (const float*)d_in[5];
    const float* ib   = (const float*)d_in[6];
    const float* uw   = (const float*)d_in[7];
    const float* ub   = (const float*)d_in[8];
    const float* ow   = (const float*)d_in[9];
    const float* ob   = (const float*)d_in[10];
    const float* w0   = (const float*)d_in[11];
    const float* b0   = (const float*)d_in[12];
    const float* w1   = (const float*)d_in[13];
    const float* b1   = (const float*)d_in[14];
    const float* w2   = (const float*)d_in[15];
    const float* b2   = (const float*)d_in[16];
    float* out = (float*)d_out;

    void *p_xp, *p_hb, *p_gx, *p_hsb, *p_z0b, *p_z1;
    void *p_wxp, *p_bias, *p_fcwp, *p_w0p, *p_w1p;
    cudaGetSymbolAddress(&p_xp,   g_xp);
    cudaGetSymbolAddress(&p_hb,   g_hb);
    cudaGetSymbolAddress(&p_gx,   g_gx);
    cudaGetSymbolAddress(&p_hsb,  g_hsb);
    cudaGetSymbolAddress(&p_z0b,  g_z0b);
    cudaGetSymbolAddress(&p_z1,   g_z1);
    cudaGetSymbolAddress(&p_wxp,  g_Wxp);
    cudaGetSymbolAddress(&p_bias, g_bias);
    cudaGetSymbolAddress(&p_fcwp, g_fcwp);
    cudaGetSymbolAddress(&p_w0p,  g_w0p);
    cudaGetSymbolAddress(&p_w1p,  g_w1p);

    cudaFuncSetAttribute(gemm_mma, cudaFuncAttributeMaxDynamicSharedMemorySize,
                         2 * STAGE_BYTES);

    // split-pack operands
    splitpack_kernel<<<(TB_ * D_ / 4) / 256, 256>>>(x, (uint32_t*)p_xp, TB_ * D_ / 4);
    splitpack_kernel<<<(H_ * D_ / 4) / 256, 256>>>(fc_w, (uint32_t*)p_fcwp, H_ * D_ / 4);
    splitpack_kernel<<<(H_ * H_ / 4) / 256, 256>>>(w0, (uint32_t*)p_w0p, H_ * H_ / 4);
    splitpack_kernel<<<(H_ * H_ / 4) / 256, 256>>>(w1, (uint32_t*)p_w1p, H_ * H_ / 4);
    pack_kernel<<<(G4_ * H_) / 256, 256>>>(fw, iw, uw, ow, fb, ib, ub, ob);

    // h = tanh(x @ fc_w^T + fc_b)   [TB,512] -> [TB,256] packed
    gemm_mma<<<dim3(H_ / 64, TB_ / 128), 256, 2 * STAGE_BYTES>>>(
        (const uint32_t*)p_xp, (const uint32_t*)p_fcwp, fc_b, p_hb, D_, H_, 1, 1);

    // gx = h @ Wx^T + bias          [TB,256] -> [TB,1024] f32
    gemm_mma<<<dim3(G4_ / 64, TB_ / 128), 256, 2 * STAGE_BYTES>>>(
        (const uint32_t*)p_hb, (const uint32_t*)p_wxp, (const float*)p_bias,
        p_gx, H_, G4_, 0, 0);

    // LSTM recurrence (persistent, per-group barrier synchronized)
    recur_kernel<<<128, 256>>>();

    // classifier
    gemm_mma<<<dim3(H_ / 64, TB_ / 128), 256, 2 * STAGE_BYTES>>>(
        (const uint32_t*)p_hsb, (const uint32_t*)p_w0p, b0, p_z0b, H_, H_, 2, 1);
    gemm_mma<<<dim3(H_ / 64, TB_ / 128), 256, 2 * STAGE_BYTES>>>(
        (const uint32_t*)p_z0b, (const uint32_t*)p_w1p, b1, p_z1, H_, H_, 2, 0);
    final_kernel<<<TB_ / 256, 256>>>((const float*)p_z1, w2, b2, out);
}

// round 11
// speedup vs baseline: 1.2852x; 1.0456x over previous
#include <cuda_runtime.h>
#include <cuda_bf16.h>
#include <math.h>
#include <stdint.h>

#define T_  1024
#define B_  128
#define D_  512
#define H_  256
#define TB_ (T_ * B_)      // 131072
#define G4_ (4 * H_)       // 1024

// ---------------- scratch (device globals; no cudaMalloc allowed) ----------
__device__ uint32_t g_xp [(size_t)TB_ * D_];   // x split-packed (hi<<16|lo)
__device__ uint32_t g_hb [(size_t)TB_ * H_];   // tanh(fc) packed
__device__ float    g_gx [(size_t)TB_ * G4_];  // gate inputs (f32, recur reads)
__device__ uint32_t g_hsb[(size_t)TB_ * H_];   // recurrence out packed
__device__ uint32_t g_z0b[(size_t)TB_ * H_];   // classifier tmp packed
__device__ float    g_z1 [(size_t)TB_ * H_];   // classifier tmp f32
__device__ uint32_t g_Wxp[G4_ * H_];           // packed input weights (f,i,u,o)
__device__ float    g_Wh [G4_ * H_];           // recurrent weights f32
__device__ float    g_bias[G4_];               // packed biases
__device__ uint32_t g_fcwp[H_ * D_];
__device__ uint32_t g_w0p[H_ * H_];
__device__ uint32_t g_w1p[H_ * H_];
__device__ float    g_hx[2 * B_ * H_];         // double-buffered hidden state
__device__ unsigned g_bar_in [16 * 32];        // per-group barrier (128B padded)
__device__ unsigned g_bar_gen[16 * 32];

// ================= helpers ==================================================
__device__ __forceinline__ uint32_t smem_u32(const void* p) {
    uint32_t a;
    asm("{ .reg .u64 t; cvta.to.shared.u64 t, %1; cvt.u32.u64 %0, t; }"
        : "=r"(a) : "l"(p));
    return a;
}

__device__ __forceinline__ void mma_bf16(float* c, const uint32_t* a,
                                         const uint32_t* b) {
    asm volatile(
        "mma.sync.aligned.m16n8k16.row.col.f32.bf16.bf16.f32 "
        "{%0,%1,%2,%3}, {%4,%5,%6,%7}, {%8,%9}, {%0,%1,%2,%3};"
        : "+f"(c[0]), "+f"(c[1]), "+f"(c[2]), "+f"(c[3])
        : "r"(a[0]), "r"(a[1]), "r"(a[2]), "r"(a[3]), "r"(b[0]), "r"(b[1]));
}

__device__ __forceinline__ void ldsm4(uint32_t* d, uint32_t addr) {
    asm volatile("ldmatrix.sync.aligned.m8n8.x4.shared.b16 {%0,%1,%2,%3}, [%4];"
        : "=r"(d[0]), "=r"(d[1]), "=r"(d[2]), "=r"(d[3]) : "r"(addr));
}

// split-pack one float: (bf16_hi << 16) | bf16_lo
__device__ __forceinline__ uint32_t pk(float v) {
    __nv_bfloat16 h = __float2bfloat16_rn(v);
    float hf = __bfloat162float(h);
    __nv_bfloat16 l = __float2bfloat16_rn(v - hf);
    return ((uint32_t)__bfloat16_as_ushort(h) << 16) | __bfloat16_as_ushort(l);
}

// packed dual fp32 FMA (SASS FFMA2)
__device__ __forceinline__ void fma2(unsigned long long& d,
                                     unsigned long long a,
                                     unsigned long long b) {
    asm("fma.rn.f32x2 %0, %1, %2, %0;" : "+l"(d) : "l"(a), "l"(b));
}

// ---------------- generic f32 -> packed splitter ---------------------------
__global__ void splitpack_kernel(const float* __restrict__ s,
                                 uint32_t* __restrict__ d, int n4) {
    int i = blockIdx.x * 256 + threadIdx.x;
    if (i < n4) {
        float4 v = ((const float4*)s)[i];
        uint4 o;
        o.x = pk(v.x); o.y = pk(v.y); o.z = pk(v.z); o.w = pk(v.w);
        ((uint4*)d)[i] = o;
    }
}

// ---------------- pack gate weights + split fc_w/w0/w1 (fused) --------------
__global__ void pack_kernel(const float* __restrict__ fw, const float* __restrict__ iw,
                            const float* __restrict__ uw, const float* __restrict__ ow,
                            const float* __restrict__ fb, const float* __restrict__ ib,
                            const float* __restrict__ ub, const float* __restrict__ ob,
                            const float* __restrict__ fcw, const float* __restrict__ w0,
                            const float* __restrict__ w1)
{
    int idx = blockIdx.x * 256 + threadIdx.x;      // 0 .. G4_*H_-1 (262144)
    int row = idx >> 8;
    int k   = idx & 255;
    int gate = row >> 8;
    int rl   = row & 255;
    const float* w = (gate == 0) ? fw : (gate == 1) ? iw : (gate == 2) ? uw : ow;
    g_Wxp[idx] = pk(w[rl * (2 * H_) + k]);
    g_Wh[idx]  = w[rl * (2 * H_) + H_ + k];
    if (idx < G4_) {
        int g2 = idx >> 8;
        const float* b = (g2 == 0) ? fb : (g2 == 1) ? ib : (g2 == 2) ? ub : ob;
        g_bias[idx] = b[idx & 255];
    }
    // fused small-weight splitting
    if (idx < H_ * D_ / 4) {                       // fc_w: 32768 float4s
        float4 v = ((const float4*)fcw)[idx];
        uint4 o; o.x = pk(v.x); o.y = pk(v.y); o.z = pk(v.z); o.w = pk(v.w);
        ((uint4*)g_fcwp)[idx] = o;
    }
    if (idx < H_ * H_ / 4) {                       // w0/w1: 16384 float4s each
        float4 v = ((const float4*)w0)[idx];
        uint4 o; o.x = pk(v.x); o.y = pk(v.y); o.z = pk(v.z); o.w = pk(v.w);
        ((uint4*)g_w0p)[idx] = o;
        v = ((const float4*)w1)[idx];
        o.x = pk(v.x); o.y = pk(v.y); o.z = pk(v.z); o.w = pk(v.w);
        ((uint4*)g_w1p)[idx] = o;
    }
}

// ================= bf16x3 mma.sync GEMM, 512 threads ========================
// C[M,N] = act(A[M,K] @ W[N,K]^T + bias). A/W u32 packed (hi<<16|lo).
// CTA tile 128x128, 512 thr (16 warps = 4M x 4N, warp tile 32x32). K-chunk 32.
// stage smem: A 16KB + B 16KB = 32KB (row = [hi u0-3 | lo u4-7], XOR swizzle);
// double buffered = 64KB. 1 CTA/SM but 16 warps = 4/SMSP.
#define STAGE_BYTES 32768
#define B_OFF 16384

__global__ void __launch_bounds__(512, 1) gemm_mma(
    const uint32_t* __restrict__ A, const uint32_t* __restrict__ W,
    const float* __restrict__ bias, void* __restrict__ Cv,
    int K, int N, int act, int outpk)
{
    extern __shared__ char smc[];
    uint32_t sbase = smem_u32(smc);
    int tid = threadIdx.x, lane = tid & 31, wid = tid >> 5;
    int m0 = blockIdx.y * 128, n0 = blockIdx.x * 128;
    int wm = (wid & 3) * 32, wn = (wid >> 2) * 32;

    // lane decode for ldmatrix addressing
    int q = lane >> 3, r = lane & 7;
    int rA0 = wm + (q & 1) * 8 + r;          // A frag rows (mt adds 16)
    int cuA = q >> 1;
    int rBb = wn + (q >> 1) * 8 + r;         // B frag rows (nt adds 16)
    int cuB = q & 1;

    // global loads: 4 thr/row, 8 u32 each (2 uint4) for both A and B
    int lrow = tid >> 2, lseg = (tid & 3) * 8;
    const uint32_t* Ag = A + (size_t)(m0 + lrow) * K + lseg;
    const uint32_t* Wg = W + (size_t)(n0 + lrow) * K + lseg;
    uint32_t sh[2], sl[2];
#pragma unroll
    for (int j = 0; j < 2; j++) {
        int col = lseg + 4 * j;
        int unit = col >> 3;
        int off = (col & 4) * 2;
        sh[j] = lrow * 128 + (((unit    ) ^ (lrow & 7)) << 4) + off;
        sl[j] = lrow * 128 + (((unit + 4) ^ (lrow & 7)) << 4) + off;
    }

    float c[2][4][4];
#pragma unroll
    for (int mt = 0; mt < 2; mt++)
#pragma unroll
        for (int f = 0; f < 4; f++)
#pragma unroll
            for (int e = 0; e < 4; e++) c[mt][f][e] = 0.f;

    int nc = K >> 5;

    // prologue: chunk 0 -> stage 0
    {
        char* st = smc;
#pragma unroll
        for (int j = 0; j < 2; j++) {
            uint4 v = *(const uint4*)&Ag[4 * j];
            uint2 hi, lo;
            hi.x = __byte_perm(v.x, v.y, 0x7632);
            lo.x = __byte_perm(v.x, v.y, 0x5410);
            hi.y = __byte_perm(v.z, v.w, 0x7632);
            lo.y = __byte_perm(v.z, v.w, 0x5410);
            *(uint2*)(st + sh[j]) = hi;
            *(uint2*)(st + sl[j]) = lo;
            v = *(const uint4*)&Wg[4 * j];
            hi.x = __byte_perm(v.x, v.y, 0x7632);
            lo.x = __byte_perm(v.x, v.y, 0x5410);
            hi.y = __byte_perm(v.z, v.w, 0x7632);
            lo.y = __byte_perm(v.z, v.w, 0x5410);
            *(uint2*)(st + B_OFF + sh[j]) = hi;
            *(uint2*)(st + B_OFF + sl[j]) = lo;
        }
    }
    __syncthreads();

#pragma unroll 1
    for (int ch = 0; ch < nc; ch++) {
        // prefetch next chunk into registers
        uint4 va[2], vw[2];
        if (ch + 1 < nc) {
            const uint32_t* Ap = Ag + (ch + 1) * 32;
            const uint32_t* Wp = Wg + (ch + 1) * 32;
#pragma unroll
            for (int j = 0; j < 2; j++) {
                va[j] = *(const uint4*)&Ap[4 * j];
                vw[j] = *(const uint4*)&Wp[4 * j];
            }
        }

        uint32_t st = sbase + (ch & 1) * STAGE_BYTES;
#pragma unroll
        for (int kk = 0; kk < 2; kk++) {
            uint32_t ah[2][4], al[2][4], bh[4][2], bl[4][2];
#pragma unroll
            for (int mt = 0; mt < 2; mt++) {
                int row = rA0 + mt * 16;
                ldsm4(ah[mt], st + row * 128 + (((cuA + kk * 2    ) ^ (row & 7)) << 4));
                ldsm4(al[mt], st + row * 128 + (((cuA + kk * 2 + 4) ^ (row & 7)) << 4));
            }
#pragma unroll
            for (int nt = 0; nt < 2; nt++) {
                int row = rBb + nt * 16;
                uint32_t t4[4];
                ldsm4(t4, st + B_OFF + row * 128 + (((cuB + kk * 2    ) ^ (row & 7)) << 4));
                bh[nt * 2][0] = t4[0]; bh[nt * 2][1] = t4[1];
                bh[nt * 2 + 1][0] = t4[2]; bh[nt * 2 + 1][1] = t4[3];
                ldsm4(t4, st + B_OFF + row * 128 + (((cuB + kk * 2 + 4) ^ (row & 7)) << 4));
                bl[nt * 2][0] = t4[0]; bl[nt * 2][1] = t4[1];
                bl[nt * 2 + 1][0] = t4[2]; bl[nt * 2 + 1][1] = t4[3];
            }
#pragma unroll
            for (int mt = 0; mt < 2; mt++)
#pragma unroll
                for (int f = 0; f < 4; f++) {
                    mma_bf16(c[mt][f], ah[mt], bh[f]);
                    mma_bf16(c[mt][f], ah[mt], bl[f]);
                    mma_bf16(c[mt][f], al[mt], bh[f]);
                }
        }

        if (ch + 1 < nc) {
            char* stw = smc + ((ch + 1) & 1) * STAGE_BYTES;
#pragma unroll
            for (int j = 0; j < 2; j++) {
                uint2 hi, lo;
                hi.x = __byte_perm(va[j].x, va[j].y, 0x7632);
                lo.x = __byte_perm(va[j].x, va[j].y, 0x5410);
                hi.y = __byte_perm(va[j].z, va[j].w, 0x7632);
                lo.y = __byte_perm(va[j].z, va[j].w, 0x5410);
                *(uint2*)(stw + sh[j]) = hi;
                *(uint2*)(stw + sl[j]) = lo;
                hi.x = __byte_perm(vw[j].x, vw[j].y, 0x7632);
                lo.x = __byte_perm(vw[j].x, vw[j].y, 0x5410);
                hi.y = __byte_perm(vw[j].z, vw[j].w, 0x7632);
                lo.y = __byte_perm(vw[j].z, vw[j].w, 0x5410);
                *(uint2*)(stw + B_OFF + sh[j]) = hi;
                *(uint2*)(stw + B_OFF + sl[j]) = lo;
            }
            __syncthreads();
        }
    }

    // epilogue: bias + activation straight from fragments
#pragma unroll
    for (int mt = 0; mt < 2; mt++) {
        int row = m0 + wm + mt * 16 + (lane >> 2);
#pragma unroll
        for (int f = 0; f < 4; f++) {
            int col = n0 + wn + f * 8 + (lane & 3) * 2;
            float b0 = __ldg(&bias[col]), b1 = __ldg(&bias[col + 1]);
            float v0 = c[mt][f][0] + b0, v1 = c[mt][f][1] + b1;
            float v2 = c[mt][f][2] + b0, v3 = c[mt][f][3] + b1;
            if (act == 1) {
                v0 = tanhf(v0); v1 = tanhf(v1); v2 = tanhf(v2); v3 = tanhf(v3);
            } else if (act == 2) {
                v0 = fmaxf(v0, 0.f); v1 = fmaxf(v1, 0.f);
                v2 = fmaxf(v2, 0.f); v3 = fmaxf(v3, 0.f);
            }
            if (outpk) {
                uint32_t* Cp = (uint32_t*)Cv;
                uint2 p01; p01.x = pk(v0); p01.y = pk(v1);
                uint2 p23; p23.x = pk(v2); p23.y = pk(v3);
                *(uint2*)&Cp[(size_t)row * N + col] = p01;
                *(uint2*)&Cp[(size_t)(row + 8) * N + col] = p23;
            } else {
                float* Cf = (float*)Cv;
                *(float2*)&Cf[(size_t)row * N + col] = make_float2(v0, v1);
                *(float2*)&Cf[(size_t)(row + 8) * N + col] = make_float2(v2, v3);
            }
        }
    }
}

// ---------------- recurrence -----------------------------------------------
__device__ __forceinline__ float sigmoidf_(float x) {
    return 1.f / (1.f + expf(-x));
}

// barrier over the 8 CTAs of one batch group (grp = bs); 128B-padded counters.
__device__ __forceinline__ void group_barrier(int grp, unsigned* s_gen_p) {
    __syncthreads();
    if (threadIdx.x == 0) {
        unsigned my = *s_gen_p;
        __threadfence();
        unsigned t = atomicAdd(&g_bar_in[grp * 32], 1u);
        if (t == 7u) {
            g_bar_in[grp * 32] = 0;
            __threadfence();
            atomicAdd(&g_bar_gen[grp * 32], 1u);
        } else {
            while (*(volatile unsigned*)&g_bar_gen[grp * 32] == my) { }
        }
        *s_gen_p = my + 1;
    }
    __syncthreads();
}

__global__ void __launch_bounds__(256, 1) recur_kernel()
{
    __shared__ float hx_sm[8 * 256];
    __shared__ float red[2 * 128 * 9];
    __shared__ unsigned s_gen;

    int tid = threadIdx.x;
    int cta = blockIdx.x;
    int bs = cta >> 3, cs = cta & 7;

    // GEMM role: register-resident Wh row-half as packed f32 pairs
    int r  = tid & 127;
    int kh = tid >> 7;
    int gg = r >> 5, jl = r & 31;
    int R = gg * H_ + cs * 32 + jl;
    unsigned long long wreg2[64];
    {
        const ulonglong2* wp = (const ulonglong2*)&g_Wh[(size_t)R * H_ + kh * 128];
#pragma unroll
        for (int qq = 0; qq < 32; qq++) {
            ulonglong2 v = wp[qq];
            wreg2[2 * qq] = v.x; wreg2[2 * qq + 1] = v.y;
        }
    }

    int b    = tid >> 5;
    int lane = tid & 31;
    int bidx = bs * 8 + b;
    int col  = cs * 32 + lane;
    float cx = 0.f;

    g_hx[bidx * H_ + col] = 0.f;
    if (tid == 0) s_gen = *(volatile unsigned*)&g_bar_gen[bs * 32];
    group_barrier(bs, &s_gen);

    for (int t = 0; t < T_; t++) {
        int cur = t & 1, nxt = cur ^ 1;

        const float* gxrow = &g_gx[((size_t)t * B_ + bidx) * G4_ + col];
        float gx0 = __ldg(&gxrow[0]);
        float gx1 = __ldg(&gxrow[256]);
        float gx2 = __ldg(&gxrow[512]);
        float gx3 = __ldg(&gxrow[768]);

        {
            const float4* src = (const float4*)&g_hx[cur * (B_ * H_) + bs * 8 * H_];
            float4* dst = (float4*)hx_sm;
            dst[tid]       = __ldcg(&src[tid]);
            dst[tid + 256] = __ldcg(&src[tid + 256]);
        }
        __syncthreads();

        // hx @ Wh^T partial via packed dual-FMA (k-split accumulators)
        unsigned long long acc2[8];
#pragma unroll
        for (int bb = 0; bb < 8; bb++) acc2[bb] = 0ULL;
        const ulonglong2* hb2 = (const ulonglong2*)(hx_sm + kh * 128);
#pragma unroll
        for (int qq = 0; qq < 32; qq++) {
#pragma unroll
            for (int bb = 0; bb < 8; bb++) {
                ulonglong2 hv = hb2[bb * 64 + qq];
                fma2(acc2[bb], wreg2[2 * qq],     hv.x);
                fma2(acc2[bb], wreg2[2 * qq + 1], hv.y);
            }
        }
#pragma unroll
        for (int bb = 0; bb < 8; bb++) {
            unsigned long long a = acc2[bb];
            float alo = __uint_as_float((uint32_t)a);
            float ahi = __uint_as_float((uint32_t)(a >> 32));
            red[(kh * 128 + r) * 9 + bb] = alo + ahi;
        }
        __syncthreads();

        float s0 = red[(0 * 32 + lane) * 9 + b] + red[(128 + 0 * 32 + lane) * 9 + b];
        float s1 = red[(1 * 32 + lane) * 9 + b] + red[(128 + 1 * 32 + lane) * 9 + b];
        float s2 = red[(2 * 32 + lane) * 9 + b] + red[(128 + 2 * 32 + lane) * 9 + b];
        float s3 = red[(3 * 32 + lane) * 9 + b] + red[(128 + 3 * 32 + lane) * 9 + b];

        float fg = sigmoidf_(s0 + gx0);
        float ig = sigmoidf_(s1 + gx1);
        float ug = tanhf(s2 + gx2);
        float og = sigmoidf_(s3 + gx3);
        cx = fg * cx + ig * ug;
        float h = og * tanhf(cx);

        g_hx[nxt * (B_ * H_) + bidx * H_ + col] = h;
        g_hsb[((size_t)t * B_ + bidx) * H_ + col] = pk(h);

        group_barrier(bs, &s_gen);
    }
}

// ---------------- final tiny projection to 2 logits ------------------------
__global__ void __launch_bounds__(256) final_kernel(
    const float* __restrict__ z, const float* __restrict__ w2,
    const float* __restrict__ b2, float* __restrict__ out)
{
    __shared__ float w[512];
    __shared__ float bb[2];
    int tid = threadIdx.x;
    w[tid] = w2[tid];
    w[tid + 256] = w2[tid + 256];
    if (tid < 2) bb[tid] = b2[tid];
    __syncthreads();

    int row = blockIdx.x * 256 + tid;
    const float4* zp = (const float4*)&z[(size_t)row * H_];
    float a0 = 0.f, a1 = 0.f;
#pragma unroll
    for (int qq = 0; qq < 64; qq++) {
        float4 v = zp[qq];
        a0 = fmaf(v.x, w[4 * qq + 0], a0);
        a0 = fmaf(v.y, w[4 * qq + 1], a0);
        a0 = fmaf(v.z, w[4 * qq + 2], a0);
        a0 = fmaf(v.w, w[4 * qq + 3], a0);
        a1 = fmaf(v.x, w[256 + 4 * qq + 0], a1);
        a1 = fmaf(v.y, w[256 + 4 * qq + 1], a1);
        a1 = fmaf(v.z, w[256 + 4 * qq + 2], a1);
        a1 = fmaf(v.w, w[256 + 4 * qq + 3], a1);
    }
    out[row * 2 + 0] = a0 + bb[0];
    out[row * 2 + 1] = a1 + bb[1];
}

// ---------------- host -----------------------------------------------------
extern "C" void kernel_launch(void* const* d_in, const int* in_sizes, int n_in,
                              void* d_out, int out_size)
{
    const float* x    = (const float*)d_in[0];
    const float* fc_w = (const float*)d_in[1];
    const float* fc_b = (const float*)d_in[2];
    const float* fw   = (const float*)d_in[3];
    const float* fb   = (const float*)d_in[4];
    const float* iw   = (const float*)d_in[5];
    const float* ib   = (const float*)d_in[6];
    const float* uw   = (const float*)d_in[7];
    const float* ub   = (const float*)d_in[8];
    const float* ow   = (const float*)d_in[9];
    const float* ob   = (const float*)d_in[10];
    const float* w0   = (const float*)d_in[11];
    const float* b0   = (const float*)d_in[12];
    const float* w1   = (const float*)d_in[13];
    const float* b1   = (const float*)d_in[14];
    const float* w2   = (const float*)d_in[15];
    const float* b2   = (const float*)d_in[16];
    float* out = (float*)d_out;

    void *p_xp, *p_hb, *p_gx, *p_hsb, *p_z0b, *p_z1;
    void *p_wxp, *p_bias, *p_fcwp, *p_w0p, *p_w1p;
    cudaGetSymbolAddress(&p_xp,   g_xp);
    cudaGetSymbolAddress(&p_hb,   g_hb);
    cudaGetSymbolAddress(&p_gx,   g_gx);
    cudaGetSymbolAddress(&p_hsb,  g_hsb);
    cudaGetSymbolAddress(&p_z0b,  g_z0b);
    cudaGetSymbolAddress(&p_z1,   g_z1);
    cudaGetSymbolAddress(&p_wxp,  g_Wxp);
    cudaGetSymbolAddress(&p_bias, g_bias);
    cudaGetSymbolAddress(&p_fcwp, g_fcwp);
    cudaGetSymbolAddress(&p_w0p,  g_w0p);
    cudaGetSymbolAddress(&p_w1p,  g_w1p);

    cudaFuncSetAttribute(gemm_mma, cudaFuncAttributeMaxDynamicSharedMemorySize,
                         2 * STAGE_BYTES);

    // slot 0: split-pack x
    splitpack_kernel<<<(TB_ * D_ / 4) / 256, 256>>>(x, (uint32_t*)p_xp, TB_ * D_ / 4);
    // slot 1: pack gate weights + fused fc_w/w0/w1 split
    pack_kernel<<<(G4_ * H_) / 256, 256>>>(fw, iw, uw, ow, fb, ib, ub, ob,
                                           fc_w, w0, w1);
    // slot 2: h = tanh(x @ fc_w^T + fc_b)   [TB,512] -> [TB,256] packed
    gemm_mma<<<dim3(H_ / 128, TB_ / 128), 512, 2 * STAGE_BYTES>>>(
        (const uint32_t*)p_xp, (const uint32_t*)p_fcwp, fc_b, p_hb, D_, H_, 1, 1);
    // slot 3 (profiled): gx = h @ Wx^T + bias   [TB,256] -> [TB,1024] f32
    gemm_mma<<<dim3(G4_ / 128, TB_ / 128), 512, 2 * STAGE_BYTES>>>(
        (const uint32_t*)p_hb, (const uint32_t*)p_wxp, (const float*)p_bias,
        p_gx, H_, G4_, 0, 0);
    // slot 4: LSTM recurrence (persistent, per-group barrier)
    recur_kernel<<<128, 256>>>();
    // slots 5-6: classifier
    gemm_mma<<<dim3(H_ / 128, TB_ / 128), 512, 2 * STAGE_BYTES>>>(
        (const uint32_t*)p_hsb, (const uint32_t*)p_w0p, b0, p_z0b, H_, H_, 2, 1);
    gemm_mma<<<dim3(H_ / 128, TB_ / 128), 512, 2 * STAGE_BYTES>>>(
        (const uint32_t*)p_z0b, (const uint32_t*)p_w1p, b1, p_z1, H_, H_, 2, 0);
    // slot 7
    final_kernel<<<TB_ / 256, 256>>>((const float*)p_z1, w2, b2, out);
}

// round 13
// speedup vs baseline: 1.6170x; 1.2582x over previous
#include <cuda_runtime.h>
#include <cuda_bf16.h>
#include <math.h>
#include <stdint.h>

#define T_  1024
#define B_  128
#define D_  512
#define H_  256
#define TB_ (T_ * B_)      // 131072
#define G4_ (4 * H_)       // 1024

// ---------------- scratch (device globals; no cudaMalloc allowed) ----------
__device__ uint32_t g_xp [(size_t)TB_ * D_];   // x split-packed (hi<<16|lo)
__device__ uint32_t g_hb [(size_t)TB_ * H_];   // tanh(fc) packed
__device__ float    g_gx [(size_t)TB_ * G4_];  // gate inputs (f32, recur reads)
__device__ uint32_t g_hsb[(size_t)TB_ * H_];   // recurrence out packed
__device__ uint32_t g_z0b[(size_t)TB_ * H_];   // classifier tmp packed
__device__ float    g_z1 [(size_t)TB_ * H_];   // classifier tmp f32
__device__ uint32_t g_Wxp[G4_ * H_];           // packed input weights (f,i,u,o)
__device__ float    g_Wh [G4_ * H_];           // recurrent weights f32
__device__ float    g_bias[G4_];               // packed biases
__device__ uint32_t g_fcwp[H_ * D_];
__device__ uint32_t g_w0p[H_ * H_];
__device__ uint32_t g_w1p[H_ * H_];
__device__ uint32_t g_hxp[2 * B_ * H_];        // double-buffered hx (packed u32)
__device__ unsigned g_bar_in [16 * 32];        // per-group barrier (128B padded)
__device__ unsigned g_bar_gen[16 * 32];

// ================= helpers ==================================================
__device__ __forceinline__ uint32_t smem_u32(const void* p) {
    uint32_t a;
    asm("{ .reg .u64 t; cvta.to.shared.u64 t, %1; cvt.u32.u64 %0, t; }"
        : "=r"(a) : "l"(p));
    return a;
}

__device__ __forceinline__ void mma_bf16(float* c, const uint32_t* a,
                                         const uint32_t* b) {
    asm volatile(
        "mma.sync.aligned.m16n8k16.row.col.f32.bf16.bf16.f32 "
        "{%0,%1,%2,%3}, {%4,%5,%6,%7}, {%8,%9}, {%0,%1,%2,%3};"
        : "+f"(c[0]), "+f"(c[1]), "+f"(c[2]), "+f"(c[3])
        : "r"(a[0]), "r"(a[1]), "r"(a[2]), "r"(a[3]), "r"(b[0]), "r"(b[1]));
}

__device__ __forceinline__ void ldsm4(uint32_t* d, uint32_t addr) {
    asm volatile("ldmatrix.sync.aligned.m8n8.x4.shared.b16 {%0,%1,%2,%3}, [%4];"
        : "=r"(d[0]), "=r"(d[1]), "=r"(d[2]), "=r"(d[3]) : "r"(addr));
}

// split-pack one float: (bf16_hi << 16) | bf16_lo
__device__ __forceinline__ uint32_t pk(float v) {
    __nv_bfloat16 h = __float2bfloat16_rn(v);
    float hf = __bfloat162float(h);
    __nv_bfloat16 l = __float2bfloat16_rn(v - hf);
    return ((uint32_t)__bfloat16_as_ushort(h) << 16) | __bfloat16_as_ushort(l);
}

// split float2 into mma-operand pairs: hi = (bf16(v.x) | bf16(v.y)<<16)
__device__ __forceinline__ void pksplit2(float2 v, uint32_t& hi, uint32_t& lo) {
    __nv_bfloat16 h0 = __float2bfloat16_rn(v.x);
    __nv_bfloat16 h1 = __float2bfloat16_rn(v.y);
    __nv_bfloat16 l0 = __float2bfloat16_rn(v.x - __bfloat162float(h0));
    __nv_bfloat16 l1 = __float2bfloat16_rn(v.y - __bfloat162float(h1));
    hi = (uint32_t)__bfloat16_as_ushort(h0) |
         ((uint32_t)__bfloat16_as_ushort(h1) << 16);
    lo = (uint32_t)__bfloat16_as_ushort(l0) |
         ((uint32_t)__bfloat16_as_ushort(l1) << 16);
}

// ---------------- generic f32 -> packed splitter ---------------------------
__global__ void splitpack_kernel(const float* __restrict__ s,
                                 uint32_t* __restrict__ d, int n4) {
    int i = blockIdx.x * 256 + threadIdx.x;
    if (i < n4) {
        float4 v = ((const float4*)s)[i];
        uint4 o;
        o.x = pk(v.x); o.y = pk(v.y); o.z = pk(v.z); o.w = pk(v.w);
        ((uint4*)d)[i] = o;
    }
}

// ---------------- pack gate weights + split fc_w/w0/w1 (fused) --------------
__global__ void pack_kernel(const float* __restrict__ fw, const float* __restrict__ iw,
                            const float* __restrict__ uw, const float* __restrict__ ow,
                            const float* __restrict__ fb, const float* __restrict__ ib,
                            const float* __restrict__ ub, const float* __restrict__ ob,
                            const float* __restrict__ fcw, const float* __restrict__ w0,
                            const float* __restrict__ w1)
{
    int idx = blockIdx.x * 256 + threadIdx.x;      // 0 .. G4_*H_-1
    int row = idx >> 8;
    int k   = idx & 255;
    int gate = row >> 8;
    int rl   = row & 255;
    const float* w = (gate == 0) ? fw : (gate == 1) ? iw : (gate == 2) ? uw : ow;
    g_Wxp[idx] = pk(w[rl * (2 * H_) + k]);
    g_Wh[idx]  = w[rl * (2 * H_) + H_ + k];
    if (idx < G4_) {
        int g2 = idx >> 8;
        const float* b = (g2 == 0) ? fb : (g2 == 1) ? ib : (g2 == 2) ? ub : ob;
        g_bias[idx] = b[idx & 255];
    }
    if (idx < H_ * D_ / 4) {
        float4 v = ((const float4*)fcw)[idx];
        uint4 o; o.x = pk(v.x); o.y = pk(v.y); o.z = pk(v.z); o.w = pk(v.w);
        ((uint4*)g_fcwp)[idx] = o;
    }
    if (idx < H_ * H_ / 4) {
        float4 v = ((const float4*)w0)[idx];
        uint4 o; o.x = pk(v.x); o.y = pk(v.y); o.z = pk(v.z); o.w = pk(v.w);
        ((uint4*)g_w0p)[idx] = o;
        v = ((const float4*)w1)[idx];
        o.x = pk(v.x); o.y = pk(v.y); o.z = pk(v.z); o.w = pk(v.w);
        ((uint4*)g_w1p)[idx] = o;
    }
}

// ================= bf16x3 mma.sync GEMM (R5-proven config) ==================
// CTA tile 128x128, 256 thr (8 warps, warp tile 32x64). K-chunk 32.
#define STAGE_BYTES 32768
#define B_OFF 16384

__global__ void __launch_bounds__(256, 1) gemm_mma(
    const uint32_t* __restrict__ A, const uint32_t* __restrict__ W,
    const float* __restrict__ bias, void* __restrict__ Cv,
    int K, int N, int act, int outpk)
{
    extern __shared__ char smc[];
    uint32_t sbase = smem_u32(smc);
    int tid = threadIdx.x, lane = tid & 31, wid = tid >> 5;
    int m0 = blockIdx.y * 128, n0 = blockIdx.x * 128;
    int wm = (wid >> 1) * 32, wn = (wid & 1) * 64;

    int q = lane >> 3, r = lane & 7;
    int rA0 = wm + (q & 1) * 8 + r;
    int cuA = q >> 1;
    int rBb = wn + (q >> 1) * 8 + r;
    int cuB = q & 1;

    int lrow = tid >> 1, lseg = (tid & 1) * 16;
    const uint32_t* Ag = A + (size_t)(m0 + lrow) * K + lseg;
    const uint32_t* Wg = W + (size_t)(n0 + lrow) * K + lseg;
    uint32_t sh[4], sl[4];
#pragma unroll
    for (int j = 0; j < 4; j++) {
        int col = lseg + 4 * j;
        int unit = col >> 3;
        int off = (col & 4) * 2;
        sh[j] = lrow * 128 + (((unit    ) ^ (lrow & 7)) << 4) + off;
        sl[j] = lrow * 128 + (((unit + 4) ^ (lrow & 7)) << 4) + off;
    }

    float c[2][8][4];
#pragma unroll
    for (int mt = 0; mt < 2; mt++)
#pragma unroll
        for (int f = 0; f < 8; f++)
#pragma unroll
            for (int e = 0; e < 4; e++) c[mt][f][e] = 0.f;

    int nc = K >> 5;

    {
        char* st = smc;
#pragma unroll
        for (int j = 0; j < 4; j++) {
            uint4 v = *(const uint4*)&Ag[4 * j];
            uint2 hi, lo;
            hi.x = __byte_perm(v.x, v.y, 0x7632);
            lo.x = __byte_perm(v.x, v.y, 0x5410);
            hi.y = __byte_perm(v.z, v.w, 0x7632);
            lo.y = __byte_perm(v.z, v.w, 0x5410);
            *(uint2*)(st + sh[j]) = hi;
            *(uint2*)(st + sl[j]) = lo;
            v = *(const uint4*)&Wg[4 * j];
            hi.x = __byte_perm(v.x, v.y, 0x7632);
            lo.x = __byte_perm(v.x, v.y, 0x5410);
            hi.y = __byte_perm(v.z, v.w, 0x7632);
            lo.y = __byte_perm(v.z, v.w, 0x5410);
            *(uint2*)(st + B_OFF + sh[j]) = hi;
            *(uint2*)(st + B_OFF + sl[j]) = lo;
        }
    }
    __syncthreads();

#pragma unroll 1
    for (int ch = 0; ch < nc; ch++) {
        uint4 va[4], vw[4];
        if (ch + 1 < nc) {
            const uint32_t* Ap = Ag + (ch + 1) * 32;
            const uint32_t* Wp = Wg + (ch + 1) * 32;
#pragma unroll
            for (int j = 0; j < 4; j++) {
                va[j] = *(const uint4*)&Ap[4 * j];
                vw[j] = *(const uint4*)&Wp[4 * j];
            }
        }

        uint32_t st = sbase + (ch & 1) * STAGE_BYTES;
#pragma unroll
        for (int kk = 0; kk < 2; kk++) {
            uint32_t ah[2][4], al[2][4], bh[8][2], bl[8][2];
#pragma unroll
            for (int mt = 0; mt < 2; mt++) {
                int row = rA0 + mt * 16;
                ldsm4(ah[mt], st + row * 128 + (((cuA + kk * 2    ) ^ (row & 7)) << 4));
                ldsm4(al[mt], st + row * 128 + (((cuA + kk * 2 + 4) ^ (row & 7)) << 4));
            }
#pragma unroll
            for (int nt = 0; nt < 4; nt++) {
                int row = rBb + nt * 16;
                uint32_t t4[4];
                ldsm4(t4, st + B_OFF + row * 128 + (((cuB + kk * 2    ) ^ (row & 7)) << 4));
                bh[nt * 2][0] = t4[0]; bh[nt * 2][1] = t4[1];
                bh[nt * 2 + 1][0] = t4[2]; bh[nt * 2 + 1][1] = t4[3];
                ldsm4(t4, st + B_OFF + row * 128 + (((cuB + kk * 2 + 4) ^ (row & 7)) << 4));
                bl[nt * 2][0] = t4[0]; bl[nt * 2][1] = t4[1];
                bl[nt * 2 + 1][0] = t4[2]; bl[nt * 2 + 1][1] = t4[3];
            }
#pragma unroll
            for (int mt = 0; mt < 2; mt++)
#pragma unroll
                for (int f = 0; f < 8; f++) {
                    mma_bf16(c[mt][f], ah[mt], bh[f]);
                    mma_bf16(c[mt][f], ah[mt], bl[f]);
                    mma_bf16(c[mt][f], al[mt], bh[f]);
                }
        }

        if (ch + 1 < nc) {
            char* stw = smc + ((ch + 1) & 1) * STAGE_BYTES;
#pragma unroll
            for (int j = 0; j < 4; j++) {
                uint2 hi, lo;
                hi.x = __byte_perm(va[j].x, va[j].y, 0x7632);
                lo.x = __byte_perm(va[j].x, va[j].y, 0x5410);
                hi.y = __byte_perm(va[j].z, va[j].w, 0x7632);
                lo.y = __byte_perm(va[j].z, va[j].w, 0x5410);
                *(uint2*)(stw + sh[j]) = hi;
                *(uint2*)(stw + sl[j]) = lo;
                hi.x = __byte_perm(vw[j].x, vw[j].y, 0x7632);
                lo.x = __byte_perm(vw[j].x, vw[j].y, 0x5410);
                hi.y = __byte_perm(vw[j].z, vw[j].w, 0x7632);
                lo.y = __byte_perm(vw[j].z, vw[j].w, 0x5410);
                *(uint2*)(stw + B_OFF + sh[j]) = hi;
                *(uint2*)(stw + B_OFF + sl[j]) = lo;
            }
            __syncthreads();
        }
    }

#pragma unroll
    for (int mt = 0; mt < 2; mt++) {
        int row = m0 + wm + mt * 16 + (lane >> 2);
#pragma unroll
        for (int f = 0; f < 8; f++) {
            int col = n0 + wn + f * 8 + (lane & 3) * 2;
            float b0 = __ldg(&bias[col]), b1 = __ldg(&bias[col + 1]);
            float v0 = c[mt][f][0] + b0, v1 = c[mt][f][1] + b1;
            float v2 = c[mt][f][2] + b0, v3 = c[mt][f][3] + b1;
            if (act == 1) {
                v0 = tanhf(v0); v1 = tanhf(v1); v2 = tanhf(v2); v3 = tanhf(v3);
            } else if (act == 2) {
                v0 = fmaxf(v0, 0.f); v1 = fmaxf(v1, 0.f);
                v2 = fmaxf(v2, 0.f); v3 = fmaxf(v3, 0.f);
            }
            if (outpk) {
                uint32_t* Cp = (uint32_t*)Cv;
                uint2 p01; p01.x = pk(v0); p01.y = pk(v1);
                uint2 p23; p23.x = pk(v2); p23.y = pk(v3);
                *(uint2*)&Cp[(size_t)row * N + col] = p01;
                *(uint2*)&Cp[(size_t)(row + 8) * N + col] = p23;
            } else {
                float* Cf = (float*)Cv;
                *(float2*)&Cf[(size_t)row * N + col] = make_float2(v0, v1);
                *(float2*)&Cf[(size_t)(row + 8) * N + col] = make_float2(v2, v3);
            }
        }
    }
}

// ---------------- recurrence: tensor-core inner GEMM ------------------------
__device__ __forceinline__ float sigmoidf_(float x) {
    return 1.f / (1.f + expf(-x));
}

// barrier over the 8 CTAs of one batch group; 128B-padded counters.
__device__ __forceinline__ void group_barrier(int grp, unsigned* s_gen_p) {
    __syncthreads();
    if (threadIdx.x == 0) {
        unsigned my = *s_gen_p;
        __threadfence();
        unsigned t = atomicAdd(&g_bar_in[grp * 32], 1u);
        if (t == 7u) {
            g_bar_in[grp * 32] = 0;
            __threadfence();
            atomicAdd(&g_bar_gen[grp * 32], 1u);
        } else {
            while (*(volatile unsigned*)&g_bar_gen[grp * 32] == my) { }
        }
        *s_gen_p = my + 1;
    }
    __syncthreads();
}

// 128 CTAs: cta = bs*8 + cs. CTA owns batch rows [8bs,8bs+8) and gate-row
// slice {g*256 + cs*32 + j}. Inner GEMM via mma.sync m16n8k16:
// A = Wh slice (M=128, register-resident bf16 hi/lo frags, step-invariant),
// B = hx (N=8 batch, bf16x3-packed u32 exchanged through L2).
#define HXS_STRIDE 260

__global__ void __launch_bounds__(256, 1) recur_kernel()
{
    __shared__ uint32_t hxs[8 * HXS_STRIDE];   // packed hx [n][k], pad 4
    __shared__ float red[128 * 9];
    __shared__ unsigned s_gen;

    int tid = threadIdx.x;
    int lane = tid & 31, w = tid >> 5;
    int cta = blockIdx.x;
    int bs = cta >> 3, cs = cta & 7;

    // ---- step-invariant A fragments: Wh slice as bf16 hi/lo ----
    int r0 = lane >> 2;              // 0..7
    int q2 = (lane & 3) * 2;         // 0,2,4,6
    int s0 = w * 16 + r0;
    int s1 = s0 + 8;
    int Ra = (s0 >> 5) * 256 + cs * 32 + (s0 & 31);  // row in packed Wh[1024]
    int Rb = (s1 >> 5) * 256 + cs * 32 + (s1 & 31);
    uint32_t ahi[16][4], alo[16][4];
#pragma unroll
    for (int kt = 0; kt < 16; kt++) {
        int k0 = kt * 16 + q2;
        pksplit2(*(const float2*)&g_Wh[(size_t)Ra * H_ + k0],     ahi[kt][0], alo[kt][0]);
        pksplit2(*(const float2*)&g_Wh[(size_t)Rb * H_ + k0],     ahi[kt][1], alo[kt][1]);
        pksplit2(*(const float2*)&g_Wh[(size_t)Ra * H_ + k0 + 8], ahi[kt][2], alo[kt][2]);
        pksplit2(*(const float2*)&g_Wh[(size_t)Rb * H_ + k0 + 8], ahi[kt][3], alo[kt][3]);
    }

    // gating role
    int b    = tid >> 5;             // 0..7 (batch within group)
    int bidx = bs * 8 + b;
    int col  = cs * 32 + lane;
    float cx = 0.f;

    g_hxp[bidx * H_ + col] = 0u;     // zero buffer 0
    if (tid == 0) s_gen = *(volatile unsigned*)&g_bar_gen[bs * 32];
    group_barrier(bs, &s_gen);

    for (int t = 0; t < T_; t++) {
        int cur = t & 1, nxt = cur ^ 1;

        // prefetch gate inputs (independent of hx)
        const float* gxrow = &g_gx[((size_t)t * B_ + bidx) * G4_ + col];
        float gx0 = __ldg(&gxrow[0]);
        float gx1 = __ldg(&gxrow[256]);
        float gx2 = __ldg(&gxrow[512]);
        float gx3 = __ldg(&gxrow[768]);

        // load this group's hx (packed) into smem [n][k] with stride pad
        {
            const uint4* src = (const uint4*)&g_hxp[cur * (B_ * H_) + bs * 8 * H_];
            uint4 v0 = __ldcg(&src[tid * 2]);
            uint4 v1 = __ldcg(&src[tid * 2 + 1]);
            int f = tid * 8;
            int n = f >> 8, k = f & 255;
            *(uint4*)&hxs[n * HXS_STRIDE + k]     = v0;
            *(uint4*)&hxs[n * HXS_STRIDE + k + 4] = v1;
        }
        __syncthreads();

        // G[128 slice, 8 batch] = Wh_slice @ hx^T via bf16x3 mma
        float c[4] = {0.f, 0.f, 0.f, 0.f};
#pragma unroll
        for (int kt = 0; kt < 16; kt++) {
            int kb = kt * 16 + q2;
            uint2 u0 = *(const uint2*)&hxs[r0 * HXS_STRIDE + kb];
            uint2 u1 = *(const uint2*)&hxs[r0 * HXS_STRIDE + kb + 8];
            uint32_t bh[2], bl[2];
            bh[0] = __byte_perm(u0.x, u0.y, 0x7632);
            bl[0] = __byte_perm(u0.x, u0.y, 0x5410);
            bh[1] = __byte_perm(u1.x, u1.y, 0x7632);
            bl[1] = __byte_perm(u1.x, u1.y, 0x5410);
            mma_bf16(c, ahi[kt], bh);
            mma_bf16(c, ahi[kt], bl);
            mma_bf16(c, alo[kt], bh);
        }

        // scatter C frags: red[s][n]  (s = slice row, n = batch)
        red[s0 * 9 + q2]     = c[0];
        red[s0 * 9 + q2 + 1] = c[1];
        red[s1 * 9 + q2]     = c[2];
        red[s1 * 9 + q2 + 1] = c[3];
        __syncthreads();

        // gather 4 gates for (bidx, col) and apply gating
        float sf = red[(0 * 32 + lane) * 9 + b];
        float si = red[(1 * 32 + lane) * 9 + b];
        float su = red[(2 * 32 + lane) * 9 + b];
        float so = red[(3 * 32 + lane) * 9 + b];

        float fg = sigmoidf_(sf + gx0);
        float ig = sigmoidf_(si + gx1);
        float ug = tanhf(su + gx2);
        float og = sigmoidf_(so + gx3);
        cx = fg * cx + ig * ug;
        float h = og * tanhf(cx);

        uint32_t hp = pk(h);
        g_hxp[nxt * (B_ * H_) + bidx * H_ + col] = hp;
        g_hsb[((size_t)t * B_ + bidx) * H_ + col] = hp;

        group_barrier(bs, &s_gen);
    }
}

// ---------------- final tiny projection to 2 logits ------------------------
__global__ void __launch_bounds__(256) final_kernel(
    const float* __restrict__ z, const float* __restrict__ w2,
    const float* __restrict__ b2, float* __restrict__ out)
{
    __shared__ float w[512];
    __shared__ float bb[2];
    int tid = threadIdx.x;
    w[tid] = w2[tid];
    w[tid + 256] = w2[tid + 256];
    if (tid < 2) bb[tid] = b2[tid];
    __syncthreads();

    int row = blockIdx.x * 256 + tid;
    const float4* zp = (const float4*)&z[(size_t)row * H_];
    float a0 = 0.f, a1 = 0.f;
#pragma unroll
    for (int qq = 0; qq < 64; qq++) {
        float4 v = zp[qq];
        a0 = fmaf(v.x, w[4 * qq + 0], a0);
        a0 = fmaf(v.y, w[4 * qq + 1], a0);
        a0 = fmaf(v.z, w[4 * qq + 2], a0);
        a0 = fmaf(v.w, w[4 * qq + 3], a0);
        a1 = fmaf(v.x, w[256 + 4 * qq + 0], a1);
        a1 = fmaf(v.y, w[256 + 4 * qq + 1], a1);
        a1 = fmaf(v.z, w[256 + 4 * qq + 2], a1);
        a1 = fmaf(v.w, w[256 + 4 * qq + 3], a1);
    }
    out[row * 2 + 0] = a0 + bb[0];
    out[row * 2 + 1] = a1 + bb[1];
}

// ---------------- host -----------------------------------------------------
extern "C" void kernel_launch(void* const* d_in, const int* in_sizes, int n_in,
                              void* d_out, int out_size)
{
    const float* x    = (const float*)d_in[0];
    const float* fc_w = (const float*)d_in[1];
    const float* fc_b = (const float*)d_in[2];
    const float* fw   = (const float*)d_in[3];
    const float* fb   = (const float*)d_in[4];
    const float* iw   = (const float*)d_in[5];
    const float* ib   = (const float*)d_in[6];
    const float* uw   = (const float*)d_in[7];
    const float* ub   = (const float*)d_in[8];
    const float* ow   = (const float*)d_in[9];
    const float* ob   = (const float*)d_in[10];
    const float* w0   = (const float*)d_in[11];
    const float* b0   = (const float*)d_in[12];
    const float* w1   = (const float*)d_in[13];
    const float* b1   = (const float*)d_in[14];
    const float* w2   = (const float*)d_in[15];
    const float* b2   = (const float*)d_in[16];
    float* out = (float*)d_out;

    void *p_xp, *p_hb, *p_gx, *p_hsb, *p_z0b, *p_z1;
    void *p_wxp, *p_bias, *p_fcwp, *p_w0p, *p_w1p;
    cudaGetSymbolAddress(&p_xp,   g_xp);
    cudaGetSymbolAddress(&p_hb,   g_hb);
    cudaGetSymbolAddress(&p_gx,   g_gx);
    cudaGetSymbolAddress(&p_hsb,  g_hsb);
    cudaGetSymbolAddress(&p_z0b,  g_z0b);
    cudaGetSymbolAddress(&p_z1,   g_z1);
    cudaGetSymbolAddress(&p_wxp,  g_Wxp);
    cudaGetSymbolAddress(&p_bias, g_bias);
    cudaGetSymbolAddress(&p_fcwp, g_fcwp);
    cudaGetSymbolAddress(&p_w0p,  g_w0p);
    cudaGetSymbolAddress(&p_w1p,  g_w1p);

    cudaFuncSetAttribute(gemm_mma, cudaFuncAttributeMaxDynamicSharedMemorySize,
                         2 * STAGE_BYTES);

    // slot 0: split-pack x
    splitpack_kernel<<<(TB_ * D_ / 4) / 256, 256>>>(x, (uint32_t*)p_xp, TB_ * D_ / 4);
    // slot 1: pack gate weights + fused fc_w/w0/w1 split
    pack_kernel<<<(G4_ * H_) / 256, 256>>>(fw, iw, uw, ow, fb, ib, ub, ob,
                                           fc_w, w0, w1);
    // slot 2: h = tanh(x @ fc_w^T + fc_b)
    gemm_mma<<<dim3(H_ / 128, TB_ / 128), 256, 2 * STAGE_BYTES>>>(
        (const uint32_t*)p_xp, (const uint32_t*)p_fcwp, fc_b, p_hb, D_, H_, 1, 1);
    // slot 3 (profiled): gx = h @ Wx^T + bias
    gemm_mma<<<dim3(G4_ / 128, TB_ / 128), 256, 2 * STAGE_BYTES>>>(
        (const uint32_t*)p_hb, (const uint32_t*)p_wxp, (const float*)p_bias,
        p_gx, H_, G4_, 0, 0);
    // slot 4: LSTM recurrence (persistent, tensor-core inner GEMM)
    recur_kernel<<<128, 256>>>();
    // slots 5-6: classifier
    gemm_mma<<<dim3(H_ / 128, TB_ / 128), 256, 2 * STAGE_BYTES>>>(
        (const uint32_t*)p_hsb, (const uint32_t*)p_w0p, b0, p_z0b, H_, H_, 2, 1);
    gemm_mma<<<dim3(H_ / 128, TB_ / 128), 256, 2 * STAGE_BYTES>>>(
        (const uint32_t*)p_z0b, (const uint32_t*)p_w1p, b1, p_z1, H_, H_, 2, 0);
    // slot 7
    final_kernel<<<TB_ / 256, 256>>>((const float*)p_z1, w2, b2, out);
}

// round 16
// speedup vs baseline: 1.6468x; 1.0184x over previous
#include <cuda_runtime.h>
#include <cuda_bf16.h>
#include <math.h>
#include <stdint.h>

#define T_  1024
#define B_  128
#define D_  512
#define H_  256
#define TB_ (T_ * B_)      // 131072
#define G4_ (4 * H_)       // 1024

// ---------------- scratch (device globals; no cudaMalloc allowed) ----------
__device__ uint32_t g_xp [(size_t)TB_ * D_];   // x split-packed (hi<<16|lo)
__device__ uint32_t g_hb [(size_t)TB_ * H_];   // tanh(fc) packed
__device__ float    g_gx [(size_t)TB_ * G4_];  // gate inputs (f32, recur reads)
__device__ uint32_t g_hsb[(size_t)TB_ * H_];   // recurrence out packed
__device__ uint32_t g_z0b[(size_t)TB_ * H_];   // classifier tmp packed
__device__ float    g_z1 [(size_t)TB_ * H_];   // classifier tmp f32
__device__ uint32_t g_Wxp[G4_ * H_];           // packed input weights (f,i,u,o)
__device__ float    g_Wh [G4_ * H_];           // recurrent weights f32
__device__ float    g_bias[G4_];               // packed biases
__device__ uint32_t g_fcwp[H_ * D_];
__device__ uint32_t g_w0p[H_ * H_];
__device__ uint32_t g_w1p[H_ * H_];
__device__ uint32_t g_hxp[2 * B_ * H_];        // double-buffered hx (packed u32)
__device__ unsigned g_bar_in [16 * 32];        // per-group barrier (128B padded)
__device__ unsigned g_bar_gen[16 * 32];

// ================= helpers ==================================================
__device__ __forceinline__ uint32_t smem_u32(const void* p) {
    uint32_t a;
    asm("{ .reg .u64 t; cvta.to.shared.u64 t, %1; cvt.u32.u64 %0, t; }"
        : "=r"(a) : "l"(p));
    return a;
}

__device__ __forceinline__ void mma_bf16(float* c, const uint32_t* a,
                                         const uint32_t* b) {
    asm volatile(
        "mma.sync.aligned.m16n8k16.row.col.f32.bf16.bf16.f32 "
        "{%0,%1,%2,%3}, {%4,%5,%6,%7}, {%8,%9}, {%0,%1,%2,%3};"
        : "+f"(c[0]), "+f"(c[1]), "+f"(c[2]), "+f"(c[3])
        : "r"(a[0]), "r"(a[1]), "r"(a[2]), "r"(a[3]), "r"(b[0]), "r"(b[1]));
}

__device__ __forceinline__ void ldsm4(uint32_t* d, uint32_t addr) {
    asm volatile("ldmatrix.sync.aligned.m8n8.x4.shared.b16 {%0,%1,%2,%3}, [%4];"
        : "=r"(d[0]), "=r"(d[1]), "=r"(d[2]), "=r"(d[3]) : "r"(addr));
}

// split-pack one float: (bf16_hi << 16) | bf16_lo
__device__ __forceinline__ uint32_t pk(float v) {
    __nv_bfloat16 h = __float2bfloat16_rn(v);
    float hf = __bfloat162float(h);
    __nv_bfloat16 l = __float2bfloat16_rn(v - hf);
    return ((uint32_t)__bfloat16_as_ushort(h) << 16) | __bfloat16_as_ushort(l);
}

// split float2 into mma-operand pairs: hi = (bf16(v.x) | bf16(v.y)<<16)
__device__ __forceinline__ void pksplit2(float2 v, uint32_t& hi, uint32_t& lo) {
    __nv_bfloat16 h0 = __float2bfloat16_rn(v.x);
    __nv_bfloat16 h1 = __float2bfloat16_rn(v.y);
    __nv_bfloat16 l0 = __float2bfloat16_rn(v.x - __bfloat162float(h0));
    __nv_bfloat16 l1 = __float2bfloat16_rn(v.y - __bfloat162float(h1));
    hi = (uint32_t)__bfloat16_as_ushort(h0) |
         ((uint32_t)__bfloat16_as_ushort(h1) << 16);
    lo = (uint32_t)__bfloat16_as_ushort(l0) |
         ((uint32_t)__bfloat16_as_ushort(l1) << 16);
}

// acquire/release atomics (replace MEMBAR-based barrier)
__device__ __forceinline__ unsigned atom_add_acqrel(unsigned* p, unsigned v) {
    unsigned old;
    asm volatile("atom.acq_rel.gpu.global.add.u32 %0, [%1], %2;"
                 : "=r"(old) : "l"(p), "r"(v) : "memory");
    return old;
}
__device__ __forceinline__ unsigned ld_acq(const unsigned* p) {
    unsigned v;
    asm volatile("ld.acquire.gpu.global.u32 %0, [%1];"
                 : "=r"(v) : "l"(p) : "memory");
    return v;
}
__device__ __forceinline__ void red_release(unsigned* p, unsigned v) {
    asm volatile("red.release.gpu.global.add.u32 [%0], %1;"
                 :: "l"(p), "r"(v) : "memory");
}

// fast gating (MUFU-based, overflow-safe)
__device__ __forceinline__ float ftanh_(float x) {
    float ax = fabsf(x);
    float e = __expf(-2.f * ax);
    float r = __fdividef(1.f - e, 1.f + e);
    return copysignf(r, x);
}
__device__ __forceinline__ float fsigm(float x) {
    return fmaf(0.5f, ftanh_(0.5f * x), 0.5f);
}

// ---------------- fused pack: x split + gate weights + fc_w/w0/w1 ----------
__global__ void pack_all_kernel(const float* __restrict__ x,
                            const float* __restrict__ fw, const float* __restrict__ iw,
                            const float* __restrict__ uw, const float* __restrict__ ow,
                            const float* __restrict__ fb, const float* __restrict__ ib,
                            const float* __restrict__ ub, const float* __restrict__ ob,
                            const float* __restrict__ fcw, const float* __restrict__ w0,
                            const float* __restrict__ w1)
{
    int idx = blockIdx.x * 256 + threadIdx.x;      // grid covers TB_*D_/4
    {   // x split-pack (all blocks)
        float4 v = ((const float4*)x)[idx];
        uint4 o;
        o.x = pk(v.x); o.y = pk(v.y); o.z = pk(v.z); o.w = pk(v.w);
        ((uint4*)g_xp)[idx] = o;
    }
    if (idx < G4_ * H_) {
        int row = idx >> 8;
        int k   = idx & 255;
        int gate = row >> 8;
        int rl   = row & 255;
        const float* w = (gate == 0) ? fw : (gate == 1) ? iw : (gate == 2) ? uw : ow;
        g_Wxp[idx] = pk(w[rl * (2 * H_) + k]);
        g_Wh[idx]  = w[rl * (2 * H_) + H_ + k];
        if (idx < G4_) {
            int g2 = idx >> 8;
            const float* b = (g2 == 0) ? fb : (g2 == 1) ? ib : (g2 == 2) ? ub : ob;
            g_bias[idx] = b[idx & 255];
        }
        if (idx < H_ * D_ / 4) {
            float4 v = ((const float4*)fcw)[idx];
            uint4 o; o.x = pk(v.x); o.y = pk(v.y); o.z = pk(v.z); o.w = pk(v.w);
            ((uint4*)g_fcwp)[idx] = o;
        }
        if (idx < H_ * H_ / 4) {
            float4 v = ((const float4*)w0)[idx];
            uint4 o; o.x = pk(v.x); o.y = pk(v.y); o.z = pk(v.z); o.w = pk(v.w);
            ((uint4*)g_w0p)[idx] = o;
            v = ((const float4*)w1)[idx];
            o.x = pk(v.x); o.y = pk(v.y); o.z = pk(v.z); o.w = pk(v.w);
            ((uint4*)g_w1p)[idx] = o;
        }
    }
}

// ================= bf16x3 mma.sync GEMM (R13-proven config) =================
// CTA tile 128x128, 256 thr (8 warps, warp tile 32x64). K-chunk 32.
#define STAGE_BYTES 32768
#define B_OFF 16384

__global__ void __launch_bounds__(256, 1) gemm_mma(
    const uint32_t* __restrict__ A, const uint32_t* __restrict__ W,
    const float* __restrict__ bias, void* __restrict__ Cv,
    int K, int N, int act, int outpk)
{
    extern __shared__ char smc[];
    uint32_t sbase = smem_u32(smc);
    int tid = threadIdx.x, lane = tid & 31, wid = tid >> 5;
    int m0 = blockIdx.y * 128, n0 = blockIdx.x * 128;
    int wm = (wid >> 1) * 32, wn = (wid & 1) * 64;

    int q = lane >> 3, r = lane & 7;
    int rA0 = wm + (q & 1) * 8 + r;
    int cuA = q >> 1;
    int rBb = wn + (q >> 1) * 8 + r;
    int cuB = q & 1;

    int lrow = tid >> 1, lseg = (tid & 1) * 16;
    const uint32_t* Ag = A + (size_t)(m0 + lrow) * K + lseg;
    const uint32_t* Wg = W + (size_t)(n0 + lrow) * K + lseg;
    uint32_t sh[4], sl[4];
#pragma unroll
    for (int j = 0; j < 4; j++) {
        int col = lseg + 4 * j;
        int unit = col >> 3;
        int off = (col & 4) * 2;
        sh[j] = lrow * 128 + (((unit    ) ^ (lrow & 7)) << 4) + off;
        sl[j] = lrow * 128 + (((unit + 4) ^ (lrow & 7)) << 4) + off;
    }

    float c[2][8][4];
#pragma unroll
    for (int mt = 0; mt < 2; mt++)
#pragma unroll
        for (int f = 0; f < 8; f++)
#pragma unroll
            for (int e = 0; e < 4; e++) c[mt][f][e] = 0.f;

    int nc = K >> 5;

    {
        char* st = smc;
#pragma unroll
        for (int j = 0; j < 4; j++) {
            uint4 v = *(const uint4*)&Ag[4 * j];
            uint2 hi, lo;
            hi.x = __byte_perm(v.x, v.y, 0x7632);
            lo.x = __byte_perm(v.x, v.y, 0x5410);
            hi.y = __byte_perm(v.z, v.w, 0x7632);
            lo.y = __byte_perm(v.z, v.w, 0x5410);
            *(uint2*)(st + sh[j]) = hi;
            *(uint2*)(st + sl[j]) = lo;
            v = *(const uint4*)&Wg[4 * j];
            hi.x = __byte_perm(v.x, v.y, 0x7632);
            lo.x = __byte_perm(v.x, v.y, 0x5410);
            hi.y = __byte_perm(v.z, v.w, 0x7632);
            lo.y = __byte_perm(v.z, v.w, 0x5410);
            *(uint2*)(st + B_OFF + sh[j]) = hi;
            *(uint2*)(st + B_OFF + sl[j]) = lo;
        }
    }
    __syncthreads();

#pragma unroll 1
    for (int ch = 0; ch < nc; ch++) {
        uint4 va[4], vw[4];
        if (ch + 1 < nc) {
            const uint32_t* Ap = Ag + (ch + 1) * 32;
            const uint32_t* Wp = Wg + (ch + 1) * 32;
#pragma unroll
            for (int j = 0; j < 4; j++) {
                va[j] = *(const uint4*)&Ap[4 * j];
                vw[j] = *(const uint4*)&Wp[4 * j];
            }
        }

        uint32_t st = sbase + (ch & 1) * STAGE_BYTES;
#pragma unroll
        for (int kk = 0; kk < 2; kk++) {
            uint32_t ah[2][4], al[2][4], bh[8][2], bl[8][2];
#pragma unroll
            for (int mt = 0; mt < 2; mt++) {
                int row = rA0 + mt * 16;
                ldsm4(ah[mt], st + row * 128 + (((cuA + kk * 2    ) ^ (row & 7)) << 4));
                ldsm4(al[mt], st + row * 128 + (((cuA + kk * 2 + 4) ^ (row & 7)) << 4));
            }
#pragma unroll
            for (int nt = 0; nt < 4; nt++) {
                int row = rBb + nt * 16;
                uint32_t t4[4];
                ldsm4(t4, st + B_OFF + row * 128 + (((cuB + kk * 2    ) ^ (row & 7)) << 4));
                bh[nt * 2][0] = t4[0]; bh[nt * 2][1] = t4[1];
                bh[nt * 2 + 1][0] = t4[2]; bh[nt * 2 + 1][1] = t4[3];
                ldsm4(t4, st + B_OFF + row * 128 + (((cuB + kk * 2 + 4) ^ (row & 7)) << 4));
                bl[nt * 2][0] = t4[0]; bl[nt * 2][1] = t4[1];
                bl[nt * 2 + 1][0] = t4[2]; bl[nt * 2 + 1][1] = t4[3];
            }
#pragma unroll
            for (int mt = 0; mt < 2; mt++)
#pragma unroll
                for (int f = 0; f < 8; f++) {
                    mma_bf16(c[mt][f], ah[mt], bh[f]);
                    mma_bf16(c[mt][f], ah[mt], bl[f]);
                    mma_bf16(c[mt][f], al[mt], bh[f]);
                }
        }

        if (ch + 1 < nc) {
            char* stw = smc + ((ch + 1) & 1) * STAGE_BYTES;
#pragma unroll
            for (int j = 0; j < 4; j++) {
                uint2 hi, lo;
                hi.x = __byte_perm(va[j].x, va[j].y, 0x7632);
                lo.x = __byte_perm(va[j].x, va[j].y, 0x5410);
                hi.y = __byte_perm(va[j].z, va[j].w, 0x7632);
                lo.y = __byte_perm(va[j].z, va[j].w, 0x5410);
                *(uint2*)(stw + sh[j]) = hi;
                *(uint2*)(stw + sl[j]) = lo;
                hi.x = __byte_perm(vw[j].x, vw[j].y, 0x7632);
                lo.x = __byte_perm(vw[j].x, vw[j].y, 0x5410);
                hi.y = __byte_perm(vw[j].z, vw[j].w, 0x7632);
                lo.y = __byte_perm(vw[j].z, vw[j].w, 0x5410);
                *(uint2*)(stw + B_OFF + sh[j]) = hi;
                *(uint2*)(stw + B_OFF + sl[j]) = lo;
            }
            __syncthreads();
        }
    }

#pragma unroll
    for (int mt = 0; mt < 2; mt++) {
        int row = m0 + wm + mt * 16 + (lane >> 2);
#pragma unroll
        for (int f = 0; f < 8; f++) {
            int col = n0 + wn + f * 8 + (lane & 3) * 2;
            float b0 = __ldg(&bias[col]), b1 = __ldg(&bias[col + 1]);
            float v0 = c[mt][f][0] + b0, v1 = c[mt][f][1] + b1;
            float v2 = c[mt][f][2] + b0, v3 = c[mt][f][3] + b1;
            if (act == 1) {
                v0 = tanhf(v0); v1 = tanhf(v1); v2 = tanhf(v2); v3 = tanhf(v3);
            } else if (act == 2) {
                v0 = fmaxf(v0, 0.f); v1 = fmaxf(v1, 0.f);
                v2 = fmaxf(v2, 0.f); v3 = fmaxf(v3, 0.f);
            }
            if (outpk) {
                uint32_t* Cp = (uint32_t*)Cv;
                uint2 p01; p01.x = pk(v0); p01.y = pk(v1);
                uint2 p23; p23.x = pk(v2); p23.y = pk(v3);
                *(uint2*)&Cp[(size_t)row * N + col] = p01;
                *(uint2*)&Cp[(size_t)(row + 8) * N + col] = p23;
            } else {
                float* Cf = (float*)Cv;
                *(float2*)&Cf[(size_t)row * N + col] = make_float2(v0, v1);
                *(float2*)&Cf[(size_t)(row + 8) * N + col] = make_float2(v2, v3);
            }
        }
    }
}

// ---------------- recurrence: tensor-core inner GEMM ------------------------
// barrier over the 8 CTAs of one batch group; acq_rel atomics, no MEMBAR.
__device__ __forceinline__ void group_barrier(int grp, unsigned* s_gen_p) {
    __syncthreads();
    if (threadIdx.x == 0) {
        unsigned my = *s_gen_p;
        unsigned t = atom_add_acqrel(&g_bar_in[grp * 32], 1u);
        if (t == 7u) {
            g_bar_in[grp * 32] = 0;
            red_release(&g_bar_gen[grp * 32], 1u);
        } else {
            while (ld_acq(&g_bar_gen[grp * 32]) == my) { }
        }
        *s_gen_p = my + 1;
    }
    __syncthreads();
}

// 128 CTAs: cta = bs*8 + cs. A = Wh slice (M=128, register-resident bf16
// hi/lo, step-invariant), B = hx (N=8, bf16x3-packed via L2). 4 independent
// accumulator chains for HMMA ILP.
#define HXS_STRIDE 260

__global__ void __launch_bounds__(256, 1) recur_kernel()
{
    __shared__ uint32_t hxs[8 * HXS_STRIDE];
    __shared__ float red[128 * 9];
    __shared__ unsigned s_gen;

    int tid = threadIdx.x;
    int lane = tid & 31, w = tid >> 5;
    int cta = blockIdx.x;
    int bs = cta >> 3, cs = cta & 7;

    // step-invariant A fragments
    int r0 = lane >> 2;
    int q2 = (lane & 3) * 2;
    int s0 = w * 16 + r0;
    int s1 = s0 + 8;
    int Ra = (s0 >> 5) * 256 + cs * 32 + (s0 & 31);
    int Rb = (s1 >> 5) * 256 + cs * 32 + (s1 & 31);
    uint32_t ahi[16][4], alo[16][4];
#pragma unroll
    for (int kt = 0; kt < 16; kt++) {
        int k0 = kt * 16 + q2;
        pksplit2(*(const float2*)&g_Wh[(size_t)Ra * H_ + k0],     ahi[kt][0], alo[kt][0]);
        pksplit2(*(const float2*)&g_Wh[(size_t)Rb * H_ + k0],     ahi[kt][1], alo[kt][1]);
        pksplit2(*(const float2*)&g_Wh[(size_t)Ra * H_ + k0 + 8], ahi[kt][2], alo[kt][2]);
        pksplit2(*(const float2*)&g_Wh[(size_t)Rb * H_ + k0 + 8], ahi[kt][3], alo[kt][3]);
    }

    int b    = tid >> 5;
    int bidx = bs * 8 + b;
    int col  = cs * 32 + lane;
    float cx = 0.f;

    g_hxp[bidx * H_ + col] = 0u;
    if (tid == 0) s_gen = ld_acq(&g_bar_gen[bs * 32]);
    group_barrier(bs, &s_gen);

    for (int t = 0; t < T_; t++) {
        int cur = t & 1, nxt = cur ^ 1;

        const float* gxrow = &g_gx[((size_t)t * B_ + bidx) * G4_ + col];
        float gx0 = __ldg(&gxrow[0]);
        float gx1 = __ldg(&gxrow[256]);
        float gx2 = __ldg(&gxrow[512]);
        float gx3 = __ldg(&gxrow[768]);

        {
            const uint4* src = (const uint4*)&g_hxp[cur * (B_ * H_) + bs * 8 * H_];
            uint4 v0 = __ldcg(&src[tid * 2]);
            uint4 v1 = __ldcg(&src[tid * 2 + 1]);
            int f = tid * 8;
            int n = f >> 8, k = f & 255;
            *(uint4*)&hxs[n * HXS_STRIDE + k]     = v0;
            *(uint4*)&hxs[n * HXS_STRIDE + k + 4] = v1;
        }
        __syncthreads();

        // 4 independent accumulator chains (HMMA ILP)
        float c4[4][4];
#pragma unroll
        for (int i = 0; i < 4; i++)
#pragma unroll
            for (int e = 0; e < 4; e++) c4[i][e] = 0.f;
#pragma unroll
        for (int kt = 0; kt < 16; kt++) {
            int kb = kt * 16 + q2;
            uint2 u0 = *(const uint2*)&hxs[r0 * HXS_STRIDE + kb];
            uint2 u1 = *(const uint2*)&hxs[r0 * HXS_STRIDE + kb + 8];
            uint32_t bh[2], bl[2];
            bh[0] = __byte_perm(u0.x, u0.y, 0x7632);
            bl[0] = __byte_perm(u0.x, u0.y, 0x5410);
            bh[1] = __byte_perm(u1.x, u1.y, 0x7632);
            bl[1] = __byte_perm(u1.x, u1.y, 0x5410);
            float* cc = c4[kt & 3];
            mma_bf16(cc, ahi[kt], bh);
            mma_bf16(cc, ahi[kt], bl);
            mma_bf16(cc, alo[kt], bh);
        }
        float c[4];
#pragma unroll
        for (int e = 0; e < 4; e++)
            c[e] = (c4[0][e] + c4[1][e]) + (c4[2][e] + c4[3][e]);

        red[s0 * 9 + q2]     = c[0];
        red[s0 * 9 + q2 + 1] = c[1];
        red[s1 * 9 + q2]     = c[2];
        red[s1 * 9 + q2 + 1] = c[3];
        __syncthreads();

        float sf = red[(0 * 32 + lane) * 9 + b];
        float si = red[(1 * 32 + lane) * 9 + b];
        float su = red[(2 * 32 + lane) * 9 + b];
        float so = red[(3 * 32 + lane) * 9 + b];

        float fg = fsigm(sf + gx0);
        float ig = fsigm(si + gx1);
        float ug = ftanh_(su + gx2);
        float og = fsigm(so + gx3);
        cx = fg * cx + ig * ug;
        float h = og * ftanh_(cx);

        uint32_t hp = pk(h);
        g_hxp[nxt * (B_ * H_) + bidx * H_ + col] = hp;
        g_hsb[((size_t)t * B_ + bidx) * H_ + col] = hp;

        group_barrier(bs, &s_gen);
    }
}

// ---------------- final tiny projection to 2 logits ------------------------
__global__ void __launch_bounds__(256) final_kernel(
    const float* __restrict__ z, const float* __restrict__ w2,
    const float* __restrict__ b2, float* __restrict__ out)
{
    __shared__ float w[512];
    __shared__ float bb[2];
    int tid = threadIdx.x;
    w[tid] = w2[tid];
    w[tid + 256] = w2[tid + 256];
    if (tid < 2) bb[tid] = b2[tid];
    __syncthreads();

    int row = blockIdx.x * 256 + tid;
    const float4* zp = (const float4*)&z[(size_t)row * H_];
    float a0 = 0.f, a1 = 0.f;
#pragma unroll
    for (int qq = 0; qq < 64; qq++) {
        float4 v = zp[qq];
        a0 = fmaf(v.x, w[4 * qq + 0], a0);
        a0 = fmaf(v.y, w[4 * qq + 1], a0);
        a0 = fmaf(v.z, w[4 * qq + 2], a0);
        a0 = fmaf(v.w, w[4 * qq + 3], a0);
        a1 = fmaf(v.x, w[256 + 4 * qq + 0], a1);
        a1 = fmaf(v.y, w[256 + 4 * qq + 1], a1);
        a1 = fmaf(v.z, w[256 + 4 * qq + 2], a1);
        a1 = fmaf(v.w, w[256 + 4 * qq + 3], a1);
    }
    out[row * 2 + 0] = a0 + bb[0];
    out[row * 2 + 1] = a1 + bb[1];
}

// ---------------- host -----------------------------------------------------
extern "C" void kernel_launch(void* const* d_in, const int* in_sizes, int n_in,
                              void* d_out, int out_size)
{
    const float* x    = (const float*)d_in[0];
    const float* fc_w = (const float*)d_in[1];
    const float* fc_b = (const float*)d_in[2];
    const float* fw   = (const float*)d_in[3];
    const float* fb   = (const float*)d_in[4];
    const float* iw   = (const float*)d_in[5];
    const float* ib   = (const float*)d_in[6];
    const float* uw   = (const float*)d_in[7];
    const float* ub   = (const float*)d_in[8];
    const float* ow   = (const float*)d_in[9];
    const float* ob   = (const float*)d_in[10];
    const float* w0   = (const float*)d_in[11];
    const float* b0   = (const float*)d_in[12];
    const float* w1   = (const float*)d_in[13];
    const float* b1   = (const float*)d_in[14];
    const float* w2   = (const float*)d_in[15];
    const float* b2   = (const float*)d_in[16];
    float* out = (float*)d_out;

    void *p_xp, *p_hb, *p_gx, *p_hsb, *p_z0b, *p_z1;
    void *p_wxp, *p_bias, *p_fcwp, *p_w0p, *p_w1p;
    cudaGetSymbolAddress(&p_xp,   g_xp);
    cudaGetSymbolAddress(&p_hb,   g_hb);
    cudaGetSymbolAddress(&p_gx,   g_gx);
    cudaGetSymbolAddress(&p_hsb,  g_hsb);
    cudaGetSymbolAddress(&p_z0b,  g_z0b);
    cudaGetSymbolAddress(&p_z1,   g_z1);
    cudaGetSymbolAddress(&p_wxp,  g_Wxp);
    cudaGetSymbolAddress(&p_bias, g_bias);
    cudaGetSymbolAddress(&p_fcwp, g_fcwp);
    cudaGetSymbolAddress(&p_w0p,  g_w0p);
    cudaGetSymbolAddress(&p_w1p,  g_w1p);

    cudaFuncSetAttribute(gemm_mma, cudaFuncAttributeMaxDynamicSharedMemorySize,
                         2 * STAGE_BYTES);

    // slot 0: fused pack (x split + all weight packing)
    pack_all_kernel<<<(TB_ * D_ / 4) / 256, 256>>>(
        x, fw, iw, uw, ow, fb, ib, ub, ob, fc_w, w0, w1);
    // slot 1: h = tanh(x @ fc_w^T + fc_b)
    gemm_mma<<<dim3(H_ / 128, TB_ / 128), 256, 2 * STAGE_BYTES>>>(
        (const uint32_t*)p_xp, (const uint32_t*)p_fcwp, fc_b, p_hb, D_, H_, 1, 1);
    // slot 2: gx = h @ Wx^T + bias
    gemm_mma<<<dim3(G4_ / 128, TB_ / 128), 256, 2 * STAGE_BYTES>>>(
        (const uint32_t*)p_hb, (const uint32_t*)p_wxp, (const float*)p_bias,
        p_gx, H_, G4_, 0, 0);
    // slot 3 (profiled): LSTM recurrence
    recur_kernel<<<128, 256>>>();
    // slots 4-5: classifier
    gemm_mma<<<dim3(H_ / 128, TB_ / 128), 256, 2 * STAGE_BYTES>>>(
        (const uint32_t*)p_hsb, (const uint32_t*)p_w0p, b0, p_z0b, H_, H_, 2, 1);
    gemm_mma<<<dim3(H_ / 128, TB_ / 128), 256, 2 * STAGE_BYTES>>>(
        (const uint32_t*)p_z0b, (const uint32_t*)p_w1p, b1, p_z1, H_, H_, 2, 0);
    // slot 6
    final_kernel<<<TB_ / 256, 256>>>((const float*)p_z1, w2, b2, out);
}